// round 10
// baseline (speedup 1.0000x reference)
#include <cuda_runtime.h>
#include <cuda_fp16.h>
#include <cstdint>
#include <math.h>

#define HDIM 1024
#define GDIM 4096
#define TT 28
#define DD 28
#define BB 4096
#define KBATCH 8

// GEMM: C[4096 x 4096gates], fp16 2-term (AhBh + AhBl), per-K-chunk fused
// CTA tile 128m x 256n (64 out-cols x 4 gates), warp tile 64x64
#define KC 64
#define CPT 17            // K-chunks (16 h-chunks + 1 x-chunk)
#define NSTAGE 2
#define TILE_A 16384      // 128 x 64 fp16
#define TILE_B 32768      // 256 x 64 fp16
#define STAGE_BYTES (TILE_A + 2*TILE_B)        // 80 KB
#define SMEM_DATA (NSTAGE * STAGE_BYTES)       // 160 KB
#define MBK 32            // 4096/128 M-blocks
#define NBK 16            // 1024/64 out-blocks (256 gate-cols per CTA)

// ---------------- persistent scratch ----------------
__device__ __half g_Wh[NBK][CPT][16384];
__device__ __half g_Wl[NBK][CPT][16384];
__device__ __half g_Ah[2][MBK][16][8192];   // h tiles (fp16 rounded), ping-pong
__device__ __half g_xh[TT][MBK][8192];
__device__ float g_c[(size_t)BB * HDIM];
__device__ float g_hf[(size_t)BB * HDIM];
__device__ float g_hk[2][KBATCH * HDIM];
__device__ float g_ck[KBATCH * HDIM];
__device__ float g_gk[KBATCH][GDIM];
__device__ float g_h0[HDIM];
__device__ float g_c0[HDIM];
__device__ unsigned int g_cnt;

// ---------------- helpers ----------------
__device__ __forceinline__ float sigmoidf_(float x) { return 1.0f / (1.0f + __expf(-x)); }

// swizzled byte offset within a [rows x 64] fp16 tile (128B rows, 16B groups)
__device__ __forceinline__ uint32_t aoff(int row, int kk) {
    return (uint32_t)(row * 128 + ((((kk >> 3) ^ row) & 7) << 4) + (kk & 7) * 2);
}

__device__ __forceinline__ uint32_t smem_u32(const void* p) {
    uint32_t a;
    asm("{ .reg .u64 t; cvta.to.shared.u64 t, %1; cvt.u32.u64 %0, t; }" : "=r"(a) : "l"(p));
    return a;
}

__device__ __forceinline__ uint32_t hpack(float v0, float v1) {
    __half2 p = __floats2half2_rn(v0, v1);
    return *(uint32_t*)&p;
}

#define CP_ASYNC16(dst, src) \
    asm volatile("cp.async.cg.shared.global [%0], [%1], 16;" :: "r"(dst), "l"(src))
#define CP_COMMIT() asm volatile("cp.async.commit_group;" ::: "memory")
#define CP_WAIT1() asm volatile("cp.async.wait_group 1;" ::: "memory")

#define LDMX4(r0, r1, r2, r3, addr) \
    asm volatile("ldmatrix.sync.aligned.m8n8.x4.shared.b16 {%0,%1,%2,%3}, [%4];" \
        : "=r"(r0), "=r"(r1), "=r"(r2), "=r"(r3) : "r"(addr))
#define MMA16816(d, a, b0, b1) \
    asm volatile("mma.sync.aligned.m16n8k16.row.col.f32.f16.f16.f32 " \
        "{%0,%1,%2,%3},{%4,%5,%6,%7},{%8,%9},{%0,%1,%2,%3};" \
        : "+f"((d)[0]), "+f"((d)[1]), "+f"((d)[2]), "+f"((d)[3]) \
        : "r"((a)[0]), "r"((a)[1]), "r"((a)[2]), "r"((a)[3]), "r"(b0), "r"(b1))

// ---------------------------------------------------------------------------
// prep: fp16 hi/lo split of weights into swizzled [n][k] tiles.
// B tile row layout (256): wn = n>>6 (warp), gate = (n>>4)&3, ol = n&15
// -> W column = gate*1024 + nb*64 + wn*16 + ol
// ---------------------------------------------------------------------------
__global__ void prep_W(const float* __restrict__ Wih, const float* __restrict__ Whh)
{
    int kc = blockIdx.x, nb = blockIdx.y;
    int n = threadIdx.x & 255, kh = threadIdx.x >> 8;
    int wn = n >> 6, gate = (n >> 4) & 3, ol = n & 15;
    int col = gate * HDIM + nb * 64 + wn * 16 + ol;
    char* th = (char*)&g_Wh[nb][kc][0];
    char* tl = (char*)&g_Wl[nb][kc][0];
#pragma unroll
    for (int kk = kh * 32; kk < kh * 32 + 32; kk += 2) {
        float v0, v1;
        if (kc < 16) {
            size_t kg = (size_t)(kc * 64 + kk);
            v0 = Whh[kg * GDIM + col];
            v1 = Whh[(kg + 1) * GDIM + col];
        } else {
            v0 = (kk < DD) ? Wih[(size_t)kk * GDIM + col] : 0.f;
            v1 = (kk + 1 < DD) ? Wih[(size_t)(kk + 1) * GDIM + col] : 0.f;
        }
        float h0 = __half2float(__float2half_rn(v0));
        float h1 = __half2float(__float2half_rn(v1));
        uint32_t off = aoff(n, kk);
        *(uint32_t*)(th + off) = hpack(h0, h1);
        *(uint32_t*)(tl + off) = hpack(v0 - h0, v1 - h1);
    }
}

__global__ void prep_x(const float* __restrict__ x)
{
    int mb = blockIdx.x, t = blockIdx.y;
    int r = threadIdx.x;
    int m = mb * 128 + r;
    char* th = (char*)&g_xh[t][mb][0];
#pragma unroll
    for (int kk = 0; kk < KC; kk += 2) {
        float v0 = (kk < DD) ? x[((size_t)m * TT + t) * DD + kk] : 0.f;
        float v1 = (kk + 1 < DD) ? x[((size_t)m * TT + t) * DD + kk + 1] : 0.f;
        *(uint32_t*)(th + aoff(r, kk)) = hpack(v0, v1);
    }
}

// ---------------------------------------------------------------------------
// Data step: fp16 mma.sync GEMM (128x256 CTA tile) + fused LSTM cell
// Stage layout: [Ah 16K][Bh 32K][Bl 32K]
// ---------------------------------------------------------------------------
__device__ __forceinline__ void load_chunk(uint32_t smb, int tid, int c,
                                           int t, int pp, int mb, int nb)
{
    if (c < CPT) {
        const char* ah = (c == 16) ? (const char*)&g_xh[t][mb][0]
                                   : (const char*)&g_Ah[pp][mb][c][0];
        const char* bh = (const char*)&g_Wh[nb][c][0];
        const char* bl = (const char*)&g_Wl[nb][c][0];
        uint32_t dst = smb + (c % NSTAGE) * STAGE_BYTES;
        int o = tid * 16;
#pragma unroll
        for (int i = 0; i < 4; i++) {
            CP_ASYNC16(dst + o, ah + o);
            o += 4096;
        }
        o = tid * 16;
#pragma unroll
        for (int i = 0; i < 8; i++) {
            CP_ASYNC16(dst + TILE_A + o,          bh + o);
            CP_ASYNC16(dst + TILE_A + TILE_B + o, bl + o);
            o += 4096;
        }
    }
    CP_COMMIT();
}

__global__ void __launch_bounds__(256, 1)
data_step(const float* __restrict__ bias, int t, int pp)
{
    extern __shared__ __align__(128) char sm[];
    const uint32_t smb = smem_u32(sm);
    const int tid = threadIdx.x, wid = tid >> 5, lane = tid & 31;
    const int nb = blockIdx.x, mb = blockIdx.y;
    const int mw = (wid >> 2) * 64;       // warp m offset (0/64)
    const int wn = wid & 3;               // warp n group
    const int nw = wn * 64;               // warp B-row offset

    float acc[4][8][4];
#pragma unroll
    for (int i = 0; i < 4; i++)
#pragma unroll
        for (int j = 0; j < 8; j++)
#pragma unroll
            for (int q = 0; q < 4; q++) acc[i][j][q] = 0.f;

    load_chunk(smb, tid, 0, t, pp, mb, nb);
    load_chunk(smb, tid, 1, t, pp, mb, nb);

    // lane geometry
    const int a_row0 = mw + ((lane >> 3) & 1) * 8 + (lane & 7);   // + mi*16
    const int a_ghalf = lane >> 4;
    const int b_row0 = nw + ((lane >> 4) & 1) * 8 + (lane & 7);   // + p*16
    const int b_ghalf = (lane >> 3) & 1;

    for (int c = 0; c < CPT; c++) {
        CP_WAIT1();
        __syncthreads();
        uint32_t sAh = smb + (c % NSTAGE) * STAGE_BYTES;
        uint32_t sBh = sAh + TILE_A;
        uint32_t sBl = sBh + TILE_B;
#pragma unroll
        for (int kb = 0; kb < 4; kb++) {
            const uint32_t acsw = (uint32_t)((((2 * kb + a_ghalf) ^ a_row0) & 7) << 4);
            const uint32_t bcsw = (uint32_t)((((2 * kb + b_ghalf) ^ b_row0) & 7) << 4);
            const uint32_t brow = (uint32_t)b_row0 * 128 + bcsw;

            uint32_t ah[4][4];
#pragma unroll
            for (int mi = 0; mi < 4; mi++) {
                uint32_t ad = sAh + (uint32_t)(a_row0 + mi * 16) * 128 + acsw;
                LDMX4(ah[mi][0], ah[mi][1], ah[mi][2], ah[mi][3], ad);
            }
            // term hi
            {
                uint32_t b[16];
#pragma unroll
                for (int p = 0; p < 4; p++)
                    LDMX4(b[4*p], b[4*p+1], b[4*p+2], b[4*p+3], sBh + brow + (uint32_t)p * 2048);
#pragma unroll
                for (int p = 0; p < 4; p++)
#pragma unroll
                    for (int mi = 0; mi < 4; mi++) {
                        MMA16816(acc[mi][2*p],   ah[mi], b[4*p],   b[4*p+1]);
                        MMA16816(acc[mi][2*p+1], ah[mi], b[4*p+2], b[4*p+3]);
                    }
            }
            // term lo
            {
                uint32_t b[16];
#pragma unroll
                for (int p = 0; p < 4; p++)
                    LDMX4(b[4*p], b[4*p+1], b[4*p+2], b[4*p+3], sBl + brow + (uint32_t)p * 2048);
#pragma unroll
                for (int p = 0; p < 4; p++)
#pragma unroll
                    for (int mi = 0; mi < 4; mi++) {
                        MMA16816(acc[mi][2*p],   ah[mi], b[4*p],   b[4*p+1]);
                        MMA16816(acc[mi][2*p+1], ah[mi], b[4*p+2], b[4*p+3]);
                    }
            }
        }
        __syncthreads();
        load_chunk(smb, tid, c + NSTAGE, t, pp, mb, nb);
    }

    // ---- fused LSTM cell epilogue ----
    // acc[mi][2*g+u] holds gate g, out col = nb*64 + wn*16 + u*8 + (lane&3)*2 (+0/1)
    const int r4 = lane >> 2;
    char* th = (char*)&g_Ah[pp ^ 1][mb][nb][0];

#pragma unroll
    for (int u = 0; u < 2; u++) {
        const int o0 = nb * 64 + wn * 16 + u * 8 + (lane & 3) * 2;
        const int kk0 = o0 & 63;
        float bi0 = bias[o0],            bi1 = bias[o0 + 1];
        float bf0 = bias[HDIM + o0],     bf1 = bias[HDIM + o0 + 1];
        float bg0 = bias[2*HDIM + o0],   bg1 = bias[2*HDIM + o0 + 1];
        float bo0 = bias[3*HDIM + o0],   bo1 = bias[3*HDIM + o0 + 1];
#pragma unroll
        for (int mi = 0; mi < 4; mi++) {
#pragma unroll
            for (int b2 = 0; b2 < 2; b2++) {
                int mrow = mw + mi * 16 + r4 + b2 * 8;
                int m = mb * 128 + mrow;
                size_t cidx = (size_t)m * HDIM + o0;
                float2 cold = *(float2*)&g_c[cidx];
                float gi0 = acc[mi][0+u][b2*2], gi1 = acc[mi][0+u][b2*2+1];
                float gf0 = acc[mi][2+u][b2*2], gf1 = acc[mi][2+u][b2*2+1];
                float gg0 = acc[mi][4+u][b2*2], gg1 = acc[mi][4+u][b2*2+1];
                float go0 = acc[mi][6+u][b2*2], go1 = acc[mi][6+u][b2*2+1];
                float cn0 = sigmoidf_(gf0 + bf0) * cold.x
                          + sigmoidf_(gi0 + bi0) * tanhf(gg0 + bg0);
                float cn1 = sigmoidf_(gf1 + bf1) * cold.y
                          + sigmoidf_(gi1 + bi1) * tanhf(gg1 + bg1);
                float h0 = sigmoidf_(go0 + bo0) * tanhf(cn0);
                float h1 = sigmoidf_(go1 + bo1) * tanhf(cn1);
                *(float2*)&g_c[cidx] = make_float2(cn0, cn1);
                *(float2*)&g_hf[cidx] = make_float2(h0, h1);
                *(uint32_t*)(th + aoff(mrow, kk0)) = hpack(h0, h1);
            }
        }
    }
}

// ---------------------------------------------------------------------------
// Key pass (batch 8): split-K SIMT GEMM + fused cell (last-CTA pattern)
// ---------------------------------------------------------------------------
#define KSPLIT 32
#define KSLICE 33
__global__ void key_gemm(const float* __restrict__ key,
                         const float* __restrict__ Wih,
                         const float* __restrict__ Whh,
                         const float* __restrict__ bias,
                         int t, int p)
{
    __shared__ float hs[KBATCH][KSLICE];
    __shared__ int is_last;
    const int cb = blockIdx.x;
    const int ks = blockIdx.y;
    const int tid = threadIdx.x;
    const int k0 = ks * KSLICE;
    const int k1 = min(k0 + KSLICE, HDIM + DD);

    for (int i = tid; i < KBATCH * KSLICE; i += 256) {
        int mm = i / KSLICE, kk = k0 + i % KSLICE;
        float v = 0.f;
        if (kk < HDIM) v = g_hk[p][mm * HDIM + kk];
        else if (kk < HDIM + DD) v = key[(size_t)(mm * TT + t) * DD + (kk - HDIM)];
        hs[mm][i % KSLICE] = v;
    }
    __syncthreads();

    const int col = cb * 256 + tid;
    float acc[KBATCH];
#pragma unroll
    for (int mm = 0; mm < KBATCH; mm++) acc[mm] = 0.f;

    const int k1h = min(k1, HDIM);
    for (int kk = k0; kk < k1h; kk++) {
        float w = Whh[(size_t)kk * GDIM + col];
        int j = kk - k0;
#pragma unroll
        for (int mm = 0; mm < KBATCH; mm++) acc[mm] += hs[mm][j] * w;
    }
    for (int kk = max(k0, HDIM); kk < k1; kk++) {
        float w = Wih[(size_t)(kk - HDIM) * GDIM + col];
        int j = kk - k0;
#pragma unroll
        for (int mm = 0; mm < KBATCH; mm++) acc[mm] += hs[mm][j] * w;
    }
#pragma unroll
    for (int mm = 0; mm < KBATCH; mm++)
        atomicAdd(&g_gk[mm][col], acc[mm]);

    // last CTA performs the cell update
    __threadfence();
    if (tid == 0) {
        unsigned int n = atomicAdd(&g_cnt, 1u);
        is_last = (n == (unsigned)(gridDim.x * gridDim.y) - 1u) ? 1 : 0;
    }
    __syncthreads();
    if (is_last) {
        __threadfence();
        for (int i = tid; i < KBATCH * HDIM; i += 256) {
            int mm = i >> 10, n = i & (HDIM - 1);
            float gi = g_gk[mm][n] + bias[n];
            float gf = g_gk[mm][HDIM + n] + bias[HDIM + n];
            float gg = g_gk[mm][2 * HDIM + n] + bias[2 * HDIM + n];
            float go = g_gk[mm][3 * HDIM + n] + bias[3 * HDIM + n];
            g_gk[mm][n] = 0.f; g_gk[mm][HDIM + n] = 0.f;
            g_gk[mm][2 * HDIM + n] = 0.f; g_gk[mm][3 * HDIM + n] = 0.f;
            float cold = g_ck[mm * HDIM + n];
            float cn = sigmoidf_(gf) * cold + sigmoidf_(gi) * tanhf(gg);
            g_ck[mm * HDIM + n] = cn;
            g_hk[1 - p][mm * HDIM + n] = sigmoidf_(go) * tanhf(cn);
        }
        if (tid == 0) g_cnt = 0u;
    }
}

__global__ void key_init()
{
    int i = blockIdx.x * blockDim.x + threadIdx.x;
    if (i == 0) g_cnt = 0u;
    if (i < KBATCH * HDIM) { g_hk[0][i] = 0.f; g_ck[i] = 0.f; }
    if (i < KBATCH * GDIM) g_gk[i / GDIM][i % GDIM] = 0.f;
}

__global__ void key_mean(int p)
{
    int n = blockIdx.x * blockDim.x + threadIdx.x;
    if (n < HDIM) {
        float sh = 0.f, sc = 0.f;
        for (int m = 0; m < KBATCH; m++) {
            sh += g_hk[p][m * HDIM + n];
            sc += g_ck[m * HDIM + n];
        }
        g_h0[n] = sh * (1.0f / KBATCH);
        g_c0[n] = sc * (1.0f / KBATCH);
    }
}

// broadcast h0/c0 into A tiles + c
__global__ void bcast_init()
{
    int mb = blockIdx.x, ch = blockIdx.y;
    int r = threadIdx.x;
    int m = mb * 128 + r;
    char* th = (char*)&g_Ah[0][mb][ch][0];
#pragma unroll
    for (int kk = 0; kk < KC; kk += 2) {
        int n = ch * KC + kk;
        float v0 = g_h0[n], v1 = g_h0[n + 1];
        *(uint32_t*)(th + aoff(r, kk)) = hpack(v0, v1);
        *(float2*)&g_c[(size_t)m * HDIM + n] = make_float2(g_c0[n], g_c0[n + 1]);
    }
}

// ---------------------------------------------------------------------------
__global__ void classify(const float* __restrict__ Wcls,
                         const float* __restrict__ bcls,
                         float* __restrict__ out)
{
    int gw = (blockIdx.x * blockDim.x + threadIdx.x) >> 5;
    int lane = threadIdx.x & 31;
    if (gw >= BB) return;
    const float* hr = &g_hf[(size_t)gw * HDIM];
    float acc[10];
#pragma unroll
    for (int c = 0; c < 10; c++) acc[c] = 0.f;
    for (int k = lane; k < HDIM; k += 32) {
        float hv = hr[k];
#pragma unroll
        for (int c = 0; c < 10; c++) acc[c] += hv * Wcls[k * 10 + c];
    }
#pragma unroll
    for (int c = 0; c < 10; c++) {
#pragma unroll
        for (int off = 16; off > 0; off >>= 1)
            acc[c] += __shfl_down_sync(0xffffffffu, acc[c], off);
    }
    if (lane == 0) {
#pragma unroll
        for (int c = 0; c < 10; c++)
            out[(size_t)gw * 10 + c] = acc[c] + bcls[c];
    }
}

// ---------------------------------------------------------------------------
extern "C" void kernel_launch(void* const* d_in, const int* in_sizes, int n_in,
                              void* d_out, int out_size)
{
    const float* x    = (const float*)d_in[0];
    const float* key  = (const float*)d_in[1];
    const float* Wih  = (const float*)d_in[2];
    const float* Whh  = (const float*)d_in[3];
    const float* b    = (const float*)d_in[4];
    const float* Wcls = (const float*)d_in[5];
    const float* bcls = (const float*)d_in[6];
    float* out = (float*)d_out;

    cudaFuncSetAttribute(data_step, cudaFuncAttributeMaxDynamicSharedMemorySize,
                         SMEM_DATA);

    prep_W<<<dim3(CPT, NBK), 512>>>(Wih, Whh);
    prep_x<<<dim3(MBK, TT), 128>>>(x);

    key_init<<<(KBATCH * GDIM + 255) / 256, 256>>>();
    for (int t = 0; t < TT; t++)
        key_gemm<<<dim3(GDIM / 256, KSPLIT), 256>>>(key, Wih, Whh, b, t, t & 1);
    key_mean<<<(HDIM + 255) / 256, 256>>>(0);
    bcast_init<<<dim3(MBK, 16), 128>>>();

    dim3 grid(NBK, MBK);
    for (int t = 0; t < TT; t++)
        data_step<<<grid, 256, SMEM_DATA>>>(b, t, t & 1);

    classify<<<BB / 8, 256>>>(Wcls, bcls, out);
}

// round 11
// speedup vs baseline: 1.4009x; 1.4009x over previous
#include <cuda_runtime.h>
#include <cuda_fp16.h>
#include <cstdint>
#include <math.h>

#define HDIM 1024
#define GDIM 4096
#define TT 28
#define DD 28
#define BB 4096
#define KBATCH 8

// GEMM: C[4096 x 4096gates], fp16 2-term (AhBh + AhBl), per-K-chunk fused
// CTA tile 128m x 128n, warp tile 64x32, NSTAGE=2 -> 96KB smem -> 2 CTA/SM
#define KC 64
#define CPT 17            // K-chunks (16 h-chunks + 1 x-chunk)
#define NSTAGE 2
#define TILE_BYTES 16384  // 128 x 64 fp16
#define STAGE_BYTES 49152 // Ah + Bh + Bl
#define SMEM_DATA (NSTAGE * STAGE_BYTES)   // 96 KB
#define MBK 32            // 4096/128 M-blocks
#define NBK 32            // 1024/32 out-blocks (128 gate-cols per CTA)

// ---------------- persistent scratch ----------------
__device__ __half g_Wh[NBK][CPT][8192];
__device__ __half g_Wl[NBK][CPT][8192];
__device__ __half g_Ah[2][MBK][16][8192];   // h tiles (fp16 rounded), ping-pong
__device__ __half g_xh[TT][MBK][8192];
__device__ float g_c[(size_t)BB * HDIM];
__device__ float g_hf[(size_t)BB * HDIM];
__device__ float g_hk[2][KBATCH * HDIM];
__device__ float g_ck[KBATCH * HDIM];
__device__ float g_gk[KBATCH][GDIM];
__device__ float g_h0[HDIM];
__device__ float g_c0[HDIM];

// ---------------- helpers ----------------
__device__ __forceinline__ float sigmoidf_(float x) { return 1.0f / (1.0f + __expf(-x)); }

// swizzled byte offset within a [rows x 64] fp16 tile (128B rows, 16B groups)
__device__ __forceinline__ uint32_t aoff(int row, int kk) {
    return (uint32_t)(row * 128 + ((((kk >> 3) ^ row) & 7) << 4) + (kk & 7) * 2);
}

__device__ __forceinline__ uint32_t smem_u32(const void* p) {
    uint32_t a;
    asm("{ .reg .u64 t; cvta.to.shared.u64 t, %1; cvt.u32.u64 %0, t; }" : "=r"(a) : "l"(p));
    return a;
}

__device__ __forceinline__ uint32_t hpack(float v0, float v1) {
    __half2 p = __floats2half2_rn(v0, v1);
    return *(uint32_t*)&p;
}

#define CP_ASYNC16(dst, src) \
    asm volatile("cp.async.cg.shared.global [%0], [%1], 16;" :: "r"(dst), "l"(src))
#define CP_COMMIT() asm volatile("cp.async.commit_group;" ::: "memory")
#define CP_WAIT1() asm volatile("cp.async.wait_group 1;" ::: "memory")

#define LDMX4(r0, r1, r2, r3, addr) \
    asm volatile("ldmatrix.sync.aligned.m8n8.x4.shared.b16 {%0,%1,%2,%3}, [%4];" \
        : "=r"(r0), "=r"(r1), "=r"(r2), "=r"(r3) : "r"(addr))
#define MMA16816(d, a, b0, b1) \
    asm volatile("mma.sync.aligned.m16n8k16.row.col.f32.f16.f16.f32 " \
        "{%0,%1,%2,%3},{%4,%5,%6,%7},{%8,%9},{%0,%1,%2,%3};" \
        : "+f"((d)[0]), "+f"((d)[1]), "+f"((d)[2]), "+f"((d)[3]) \
        : "r"((a)[0]), "r"((a)[1]), "r"((a)[2]), "r"((a)[3]), "r"(b0), "r"(b1))

// ---------------------------------------------------------------------------
// prep: fp16 hi/lo split of weights into swizzled [n][k] tiles.
// B tile col layout (128): warp w (n>>5), gate ((n>>3)&3), out_local (n&7)
// -> W column = gate*1024 + nb*32 + w*8 + ol
// ---------------------------------------------------------------------------
__global__ void prep_W(const float* __restrict__ Wih, const float* __restrict__ Whh)
{
    int kc = blockIdx.x, nb = blockIdx.y;
    int n = threadIdx.x & 127, kh = threadIdx.x >> 7;
    int w = n >> 5, gate = (n >> 3) & 3, ol = n & 7;
    int col = gate * HDIM + nb * 32 + w * 8 + ol;
    char* th = (char*)&g_Wh[nb][kc][0];
    char* tl = (char*)&g_Wl[nb][kc][0];
#pragma unroll
    for (int kk = kh * 32; kk < kh * 32 + 32; kk += 2) {
        float v0, v1;
        if (kc < 16) {
            size_t kg = (size_t)(kc * 64 + kk);
            v0 = Whh[kg * GDIM + col];
            v1 = Whh[(kg + 1) * GDIM + col];
        } else {
            v0 = (kk < DD) ? Wih[(size_t)kk * GDIM + col] : 0.f;
            v1 = (kk + 1 < DD) ? Wih[(size_t)(kk + 1) * GDIM + col] : 0.f;
        }
        float h0 = __half2float(__float2half_rn(v0));
        float h1 = __half2float(__float2half_rn(v1));
        uint32_t off = aoff(n, kk);
        *(uint32_t*)(th + off) = hpack(h0, h1);
        *(uint32_t*)(tl + off) = hpack(v0 - h0, v1 - h1);
    }
}

__global__ void prep_x(const float* __restrict__ x)
{
    int mb = blockIdx.x, t = blockIdx.y;
    int r = threadIdx.x;
    int m = mb * 128 + r;
    char* th = (char*)&g_xh[t][mb][0];
#pragma unroll
    for (int kk = 0; kk < KC; kk += 2) {
        float v0 = (kk < DD) ? x[((size_t)m * TT + t) * DD + kk] : 0.f;
        float v1 = (kk + 1 < DD) ? x[((size_t)m * TT + t) * DD + kk + 1] : 0.f;
        *(uint32_t*)(th + aoff(r, kk)) = hpack(v0, v1);
    }
}

// ---------------------------------------------------------------------------
// Data step: fp16 mma.sync GEMM, 2 terms (AhBh + AhBl) + fused LSTM cell
// Stage layout: [Ah 16K][Bh 16K][Bl 16K]
// ---------------------------------------------------------------------------
__device__ __forceinline__ void load_chunk(uint32_t smb, int tid, int c,
                                           int t, int pp, int mb, int nb)
{
    if (c < CPT) {
        const char* ah = (c == 16) ? (const char*)&g_xh[t][mb][0]
                                   : (const char*)&g_Ah[pp][mb][c][0];
        const char* bh = (const char*)&g_Wh[nb][c][0];
        const char* bl = (const char*)&g_Wl[nb][c][0];
        uint32_t dst = smb + (c % NSTAGE) * STAGE_BYTES;
        int o = tid * 16;
#pragma unroll
        for (int i = 0; i < 4; i++) {
            CP_ASYNC16(dst + o,                 ah + o);
            CP_ASYNC16(dst + TILE_BYTES + o,    bh + o);
            CP_ASYNC16(dst + 2*TILE_BYTES + o,  bl + o);
            o += 4096;
        }
    }
    CP_COMMIT();
}

__global__ void __launch_bounds__(256, 2)
data_step(const float* __restrict__ bias, int t, int pp)
{
    extern __shared__ __align__(128) char sm[];
    const uint32_t smb = smem_u32(sm);
    const int tid = threadIdx.x, wid = tid >> 5, lane = tid & 31;
    const int nb = blockIdx.x, mb = blockIdx.y;
    const int mw = (wid >> 2) * 64;       // warp m offset
    const int nw = (wid & 3) * 32;        // warp n(col) offset

    float acc[4][4][4];
#pragma unroll
    for (int i = 0; i < 4; i++)
#pragma unroll
        for (int j = 0; j < 4; j++)
#pragma unroll
            for (int q = 0; q < 4; q++) acc[i][j][q] = 0.f;

    load_chunk(smb, tid, 0, t, pp, mb, nb);
    load_chunk(smb, tid, 1, t, pp, mb, nb);

    // lane geometry
    const int a_row0 = mw + ((lane >> 3) & 1) * 8 + (lane & 7);   // + mi*16
    const int a_ghalf = lane >> 4;
    // B ldmatrix.x4: m0=(ni,kh0) m1=(ni,kh1) m2=(ni+1,kh0) m3=(ni+1,kh1)
    const int b_row0 = nw + ((lane >> 4) & 1) * 8 + (lane & 7);   // + 16 for ni 2,3
    const int b_ghalf = (lane >> 3) & 1;

    for (int c = 0; c < CPT; c++) {
        CP_WAIT1();
        __syncthreads();

        uint32_t sAh = smb + (c % NSTAGE) * STAGE_BYTES;
        uint32_t sBh = sAh + TILE_BYTES;
        uint32_t sBl = sAh + 2 * TILE_BYTES;
#pragma unroll
        for (int kb = 0; kb < 4; kb++) {
            const uint32_t acsw = (uint32_t)((((2 * kb + a_ghalf) ^ a_row0) & 7) << 4);
            const uint32_t bcsw = (uint32_t)((((2 * kb + b_ghalf) ^ b_row0) & 7) << 4);
            const uint32_t brow = (uint32_t)b_row0 * 128 + bcsw;

            uint32_t ah[4][4], bh[8], bl[8];
#pragma unroll
            for (int mi = 0; mi < 4; mi++) {
                uint32_t ad = sAh + (uint32_t)(a_row0 + mi * 16) * 128 + acsw;
                LDMX4(ah[mi][0], ah[mi][1], ah[mi][2], ah[mi][3], ad);
            }
            LDMX4(bh[0], bh[1], bh[2], bh[3], sBh + brow);
            LDMX4(bh[4], bh[5], bh[6], bh[7], sBh + brow + 2048);
            LDMX4(bl[0], bl[1], bl[2], bl[3], sBl + brow);
            LDMX4(bl[4], bl[5], bl[6], bl[7], sBl + brow + 2048);
#pragma unroll
            for (int ni = 0; ni < 4; ni++)
#pragma unroll
                for (int mi = 0; mi < 4; mi++) {
                    MMA16816(acc[mi][ni], ah[mi], bh[ni * 2], bh[ni * 2 + 1]);
                    MMA16816(acc[mi][ni], ah[mi], bl[ni * 2], bl[ni * 2 + 1]);
                }
        }
        __syncthreads();
        load_chunk(smb, tid, c + NSTAGE, t, pp, mb, nb);
    }

    // ---- fused LSTM cell epilogue ----
    const int r4 = lane >> 2;
    const int o0 = nb * 32 + (wid & 3) * 8 + (lane & 3) * 2;
    const int chunk = nb >> 1;
    const int kk0 = o0 & 63;
    const int last = (t == TT - 1);
    float bi0 = bias[o0],            bi1 = bias[o0 + 1];
    float bf0 = bias[HDIM + o0],     bf1 = bias[HDIM + o0 + 1];
    float bg0 = bias[2*HDIM + o0],   bg1 = bias[2*HDIM + o0 + 1];
    float bo0 = bias[3*HDIM + o0],   bo1 = bias[3*HDIM + o0 + 1];
    char* th = (char*)&g_Ah[pp ^ 1][mb][chunk][0];

#pragma unroll
    for (int mi = 0; mi < 4; mi++) {
#pragma unroll
        for (int b2 = 0; b2 < 2; b2++) {
            int mrow = mw + mi * 16 + r4 + b2 * 8;
            int m = mb * 128 + mrow;
            size_t cidx = (size_t)m * HDIM + o0;
            float2 cold = *(float2*)&g_c[cidx];
            float gi0 = acc[mi][0][b2 * 2],     gi1 = acc[mi][0][b2 * 2 + 1];
            float gf0 = acc[mi][1][b2 * 2],     gf1 = acc[mi][1][b2 * 2 + 1];
            float gg0 = acc[mi][2][b2 * 2],     gg1 = acc[mi][2][b2 * 2 + 1];
            float go0 = acc[mi][3][b2 * 2],     go1 = acc[mi][3][b2 * 2 + 1];
            float cn0 = sigmoidf_(gf0 + bf0) * cold.x
                      + sigmoidf_(gi0 + bi0) * tanhf(gg0 + bg0);
            float cn1 = sigmoidf_(gf1 + bf1) * cold.y
                      + sigmoidf_(gi1 + bi1) * tanhf(gg1 + bg1);
            float h0 = sigmoidf_(go0 + bo0) * tanhf(cn0);
            float h1 = sigmoidf_(go1 + bo1) * tanhf(cn1);
            *(float2*)&g_c[cidx] = make_float2(cn0, cn1);
            if (last) *(float2*)&g_hf[cidx] = make_float2(h0, h1);
            *(uint32_t*)(th + aoff(mrow, kk0)) = hpack(h0, h1);
        }
    }
}

// ---------------------------------------------------------------------------
// Key pass (batch 8): split-K SIMT GEMM, one thread per column (all 8 rows)
// ---------------------------------------------------------------------------
#define KSPLIT 32
#define KSLICE 33
__global__ void key_gemm(const float* __restrict__ key,
                         const float* __restrict__ Wih,
                         const float* __restrict__ Whh,
                         int t, int p)
{
    __shared__ float hs[KBATCH][KSLICE];
    const int cb = blockIdx.x;
    const int ks = blockIdx.y;
    const int tid = threadIdx.x;
    const int k0 = ks * KSLICE;
    const int k1 = min(k0 + KSLICE, HDIM + DD);

    for (int i = tid; i < KBATCH * KSLICE; i += 256) {
        int mm = i / KSLICE, kk = k0 + i % KSLICE;
        float v = 0.f;
        if (kk < HDIM) v = g_hk[p][mm * HDIM + kk];
        else if (kk < HDIM + DD) v = key[(size_t)(mm * TT + t) * DD + (kk - HDIM)];
        hs[mm][i % KSLICE] = v;
    }
    __syncthreads();

    const int col = cb * 256 + tid;
    float acc[KBATCH];
#pragma unroll
    for (int mm = 0; mm < KBATCH; mm++) acc[mm] = 0.f;

    const int k1h = min(k1, HDIM);
    for (int kk = k0; kk < k1h; kk++) {
        float w = Whh[(size_t)kk * GDIM + col];
        int j = kk - k0;
#pragma unroll
        for (int mm = 0; mm < KBATCH; mm++) acc[mm] += hs[mm][j] * w;
    }
    for (int kk = max(k0, HDIM); kk < k1; kk++) {
        float w = Wih[(size_t)(kk - HDIM) * GDIM + col];
        int j = kk - k0;
#pragma unroll
        for (int mm = 0; mm < KBATCH; mm++) acc[mm] += hs[mm][j] * w;
    }
#pragma unroll
    for (int mm = 0; mm < KBATCH; mm++)
        atomicAdd(&g_gk[mm][col], acc[mm]);
}

__global__ void key_cell(const float* __restrict__ bias, int p)
{
    int i = blockIdx.x * blockDim.x + threadIdx.x;
    if (i >= KBATCH * HDIM) return;
    int mm = i >> 10, n = i & (HDIM - 1);
    float gi = g_gk[mm][n] + bias[n];
    float gf = g_gk[mm][HDIM + n] + bias[HDIM + n];
    float gg = g_gk[mm][2 * HDIM + n] + bias[2 * HDIM + n];
    float go = g_gk[mm][3 * HDIM + n] + bias[3 * HDIM + n];
    g_gk[mm][n] = 0.f; g_gk[mm][HDIM + n] = 0.f;
    g_gk[mm][2 * HDIM + n] = 0.f; g_gk[mm][3 * HDIM + n] = 0.f;
    float cold = g_ck[mm * HDIM + n];
    float cn = sigmoidf_(gf) * cold + sigmoidf_(gi) * tanhf(gg);
    g_ck[mm * HDIM + n] = cn;
    g_hk[1 - p][mm * HDIM + n] = sigmoidf_(go) * tanhf(cn);
}

__global__ void key_init()
{
    int i = blockIdx.x * blockDim.x + threadIdx.x;
    if (i < KBATCH * HDIM) { g_hk[0][i] = 0.f; g_ck[i] = 0.f; }
    if (i < KBATCH * GDIM) g_gk[i / GDIM][i % GDIM] = 0.f;
}

__global__ void key_mean(int p)
{
    int n = blockIdx.x * blockDim.x + threadIdx.x;
    if (n < HDIM) {
        float sh = 0.f, sc = 0.f;
        for (int m = 0; m < KBATCH; m++) {
            sh += g_hk[p][m * HDIM + n];
            sc += g_ck[m * HDIM + n];
        }
        g_h0[n] = sh * (1.0f / KBATCH);
        g_c0[n] = sc * (1.0f / KBATCH);
    }
}

// broadcast h0/c0 into A tiles + c
__global__ void bcast_init()
{
    int mb = blockIdx.x, ch = blockIdx.y;
    int r = threadIdx.x;
    int m = mb * 128 + r;
    char* th = (char*)&g_Ah[0][mb][ch][0];
#pragma unroll
    for (int kk = 0; kk < KC; kk += 2) {
        int n = ch * KC + kk;
        float v0 = g_h0[n], v1 = g_h0[n + 1];
        *(uint32_t*)(th + aoff(r, kk)) = hpack(v0, v1);
        *(float2*)&g_c[(size_t)m * HDIM + n] = make_float2(g_c0[n], g_c0[n + 1]);
    }
}

// ---------------------------------------------------------------------------
__global__ void classify(const float* __restrict__ Wcls,
                         const float* __restrict__ bcls,
                         float* __restrict__ out)
{
    int gw = (blockIdx.x * blockDim.x + threadIdx.x) >> 5;
    int lane = threadIdx.x & 31;
    if (gw >= BB) return;
    const float* hr = &g_hf[(size_t)gw * HDIM];
    float acc[10];
#pragma unroll
    for (int c = 0; c < 10; c++) acc[c] = 0.f;
    for (int k = lane; k < HDIM; k += 32) {
        float hv = hr[k];
#pragma unroll
        for (int c = 0; c < 10; c++) acc[c] += hv * Wcls[k * 10 + c];
    }
#pragma unroll
    for (int c = 0; c < 10; c++) {
#pragma unroll
        for (int off = 16; off > 0; off >>= 1)
            acc[c] += __shfl_down_sync(0xffffffffu, acc[c], off);
    }
    if (lane == 0) {
#pragma unroll
        for (int c = 0; c < 10; c++)
            out[(size_t)gw * 10 + c] = acc[c] + bcls[c];
    }
}

// ---------------------------------------------------------------------------
extern "C" void kernel_launch(void* const* d_in, const int* in_sizes, int n_in,
                              void* d_out, int out_size)
{
    const float* x    = (const float*)d_in[0];
    const float* key  = (const float*)d_in[1];
    const float* Wih  = (const float*)d_in[2];
    const float* Whh  = (const float*)d_in[3];
    const float* b    = (const float*)d_in[4];
    const float* Wcls = (const float*)d_in[5];
    const float* bcls = (const float*)d_in[6];
    float* out = (float*)d_out;

    cudaFuncSetAttribute(data_step, cudaFuncAttributeMaxDynamicSharedMemorySize,
                         SMEM_DATA);

    prep_W<<<dim3(CPT, NBK), 256>>>(Wih, Whh);
    prep_x<<<dim3(MBK, TT), 128>>>(x);

    key_init<<<(KBATCH * GDIM + 255) / 256, 256>>>();
    for (int t = 0; t < TT; t++) {
        key_gemm<<<dim3(GDIM / 256, KSPLIT), 256>>>(key, Wih, Whh, t, t & 1);
        key_cell<<<(KBATCH * HDIM + 255) / 256, 256>>>(b, t & 1);
    }
    key_mean<<<(HDIM + 255) / 256, 256>>>(0);
    bcast_init<<<dim3(MBK, 16), 128>>>();

    dim3 grid(NBK, MBK);
    for (int t = 0; t < TT; t++)
        data_step<<<grid, 256, SMEM_DATA>>>(b, t, t & 1);

    classify<<<BB / 8, 256>>>(Wcls, bcls, out);
}

// round 13
// speedup vs baseline: 1.4905x; 1.0639x over previous
#include <cuda_runtime.h>
#include <cuda_fp16.h>
#include <cstdint>
#include <math.h>

#define HDIM 1024
#define GDIM 4096
#define TT 28
#define DD 28
#define BB 4096
#define KBATCH 8

// GEMM: C[4096 x 4096gates], fp16 2-term (AhBh + AhBl), per-K-chunk fused
// CTA tile 128m x 128n, warp tile 64x32, NSTAGE=2 -> 96KB smem -> 2 CTA/SM
// Data pass = ONE persistent kernel, device-side ticket scheduler,
// per-(t,mb) dependency counters (28 independent-chain overlap).
#define KC 64
#define CPT 17            // K-chunks (16 h-chunks + 1 x-chunk)
#define NSTAGE 2
#define TILE_BYTES 16384  // 128 x 64 fp16
#define STAGE_BYTES 49152 // Ah + Bh + Bl
#define SMEM_DATA (NSTAGE * STAGE_BYTES)   // 96 KB
#define MBK 32            // 4096/128 M-blocks
#define NBK 32            // 1024/32 out-blocks (128 gate-cols per CTA)
#define NTASK (TT * MBK * NBK)
#define PGRID 296         // 2 CTAs x 148 SMs, all resident

// ---------------- persistent scratch ----------------
__device__ __half g_Wh[NBK][CPT][8192];
__device__ __half g_Wl[NBK][CPT][8192];
__device__ __half g_Ah[2][MBK][16][8192];   // h tiles (fp16 rounded), ping-pong
__device__ __half g_xh[TT][MBK][8192];
__device__ float g_c[(size_t)BB * HDIM];
__device__ float g_hf[(size_t)BB * HDIM];
__device__ float g_hk[2][KBATCH * HDIM];
__device__ float g_ck[KBATCH * HDIM];
__device__ float g_gk[KBATCH][GDIM];
__device__ float g_h0[HDIM];
__device__ float g_c0[HDIM];
__device__ unsigned int g_ticket;
__device__ unsigned int g_dep[TT][MBK];

// ---------------- helpers ----------------
__device__ __forceinline__ float sigmoidf_(float x) { return 1.0f / (1.0f + __expf(-x)); }

// swizzled byte offset within a [rows x 64] fp16 tile (128B rows, 16B groups)
__device__ __forceinline__ uint32_t aoff(int row, int kk) {
    return (uint32_t)(row * 128 + ((((kk >> 3) ^ row) & 7) << 4) + (kk & 7) * 2);
}

__device__ __forceinline__ uint32_t smem_u32(const void* p) {
    uint32_t a;
    asm("{ .reg .u64 t; cvta.to.shared.u64 t, %1; cvt.u32.u64 %0, t; }" : "=r"(a) : "l"(p));
    return a;
}

__device__ __forceinline__ uint32_t hpack(float v0, float v1) {
    __half2 p = __floats2half2_rn(v0, v1);
    return *(uint32_t*)&p;
}

#define CP_ASYNC16(dst, src) \
    asm volatile("cp.async.cg.shared.global [%0], [%1], 16;" :: "r"(dst), "l"(src))
#define CP_COMMIT() asm volatile("cp.async.commit_group;" ::: "memory")
#define CP_WAIT1() asm volatile("cp.async.wait_group 1;" ::: "memory")

#define LDMX4(r0, r1, r2, r3, addr) \
    asm volatile("ldmatrix.sync.aligned.m8n8.x4.shared.b16 {%0,%1,%2,%3}, [%4];" \
        : "=r"(r0), "=r"(r1), "=r"(r2), "=r"(r3) : "r"(addr))
#define MMA16816(d, a, b0, b1) \
    asm volatile("mma.sync.aligned.m16n8k16.row.col.f32.f16.f16.f32 " \
        "{%0,%1,%2,%3},{%4,%5,%6,%7},{%8,%9},{%0,%1,%2,%3};" \
        : "+f"((d)[0]), "+f"((d)[1]), "+f"((d)[2]), "+f"((d)[3]) \
        : "r"((a)[0]), "r"((a)[1]), "r"((a)[2]), "r"((a)[3]), "r"(b0), "r"(b1))

// ---------------------------------------------------------------------------
// prep: fp16 hi/lo split of weights into swizzled [n][k] tiles.
// B tile row layout (128): warp w (n>>5), gate ((n>>3)&3), out_local (n&7)
// -> W column = gate*1024 + nb*32 + w*8 + ol ; tile row n = w*32+gate*8+ol
// ---------------------------------------------------------------------------
__global__ void prep_W(const float* __restrict__ Wih, const float* __restrict__ Whh)
{
    int kc = blockIdx.x, nb = blockIdx.y;
    int n = threadIdx.x & 127, kh = threadIdx.x >> 7;
    int w = n >> 5, gate = (n >> 3) & 3, ol = n & 7;
    int col = gate * HDIM + nb * 32 + w * 8 + ol;
    char* th = (char*)&g_Wh[nb][kc][0];
    char* tl = (char*)&g_Wl[nb][kc][0];
#pragma unroll
    for (int kk = kh * 32; kk < kh * 32 + 32; kk += 2) {
        float v0, v1;
        if (kc < 16) {
            size_t kg = (size_t)(kc * 64 + kk);
            v0 = Whh[kg * GDIM + col];
            v1 = Whh[(kg + 1) * GDIM + col];
        } else {
            v0 = (kk < DD) ? Wih[(size_t)kk * GDIM + col] : 0.f;
            v1 = (kk + 1 < DD) ? Wih[(size_t)(kk + 1) * GDIM + col] : 0.f;
        }
        float h0 = __half2float(__float2half_rn(v0));
        float h1 = __half2float(__float2half_rn(v1));
        uint32_t off = aoff(n, kk);
        *(uint32_t*)(th + off) = hpack(h0, h1);
        *(uint32_t*)(tl + off) = hpack(v0 - h0, v1 - h1);
    }
}

__global__ void prep_x(const float* __restrict__ x)
{
    int mb = blockIdx.x, t = blockIdx.y;
    int r = threadIdx.x;
    int m = mb * 128 + r;
    char* th = (char*)&g_xh[t][mb][0];
#pragma unroll
    for (int kk = 0; kk < KC; kk += 2) {
        float v0 = (kk < DD) ? x[((size_t)m * TT + t) * DD + kk] : 0.f;
        float v1 = (kk + 1 < DD) ? x[((size_t)m * TT + t) * DD + kk + 1] : 0.f;
        *(uint32_t*)(th + aoff(r, kk)) = hpack(v0, v1);
    }
}

// ---------------------------------------------------------------------------
// Persistent data pass: device-side scheduler + fp16 GEMM + fused LSTM cell
// ---------------------------------------------------------------------------
__device__ __forceinline__ void load_chunk(uint32_t smb, int tid, int c,
                                           int t, int pp, int mb, int nb)
{
    if (c < CPT) {
        const char* ah = (c == 16) ? (const char*)&g_xh[t][mb][0]
                                   : (const char*)&g_Ah[pp][mb][c][0];
        const char* bh = (const char*)&g_Wh[nb][c][0];
        const char* bl = (const char*)&g_Wl[nb][c][0];
        uint32_t dst = smb + (c % NSTAGE) * STAGE_BYTES;
        int o = tid * 16;
#pragma unroll
        for (int i = 0; i < 4; i++) {
            CP_ASYNC16(dst + o,                 ah + o);
            CP_ASYNC16(dst + TILE_BYTES + o,    bh + o);
            CP_ASYNC16(dst + 2*TILE_BYTES + o,  bl + o);
            o += 4096;
        }
    }
    CP_COMMIT();
}

__global__ void __launch_bounds__(256, 2)
data_persist(const float* __restrict__ bias)
{
    extern __shared__ __align__(128) char sm[];
    const uint32_t smb = smem_u32(sm);
    __shared__ unsigned int s_task;
    const int tid = threadIdx.x, wid = tid >> 5, lane = tid & 31;
    const int mw = (wid >> 2) * 64;       // warp m offset
    const int nw = (wid & 3) * 32;        // warp n(col) offset

    // lane geometry (task-invariant)
    const int a_row0 = mw + ((lane >> 3) & 1) * 8 + (lane & 7);   // + mi*16
    const int a_ghalf = lane >> 4;
    const int b_row0 = nw + ((lane >> 4) & 1) * 8 + (lane & 7);   // + 16 for ni 2,3
    const int b_ghalf = (lane >> 3) & 1;
    const int r4 = lane >> 2;

    for (;;) {
        if (tid == 0) s_task = atomicAdd(&g_ticket, 1u);
        __syncthreads();
        const unsigned int task = s_task;
        if (task >= NTASK) return;
        const int t  = task >> 10;
        const int mb = (task >> 5) & 31;
        const int nb = task & 31;
        const int pp = t & 1;

        // wait for step t-1 of this mb chain
        if (t > 0 && tid == 0) {
            const unsigned int* dp = &g_dep[t - 1][mb];
            unsigned int v;
            for (;;) {
                asm volatile("ld.acquire.gpu.global.u32 %0, [%1];" : "=r"(v) : "l"(dp));
                if (v >= NBK) break;
                __nanosleep(128);
            }
        }
        __syncthreads();

        float acc[4][4][4];
#pragma unroll
        for (int i = 0; i < 4; i++)
#pragma unroll
            for (int j = 0; j < 4; j++)
#pragma unroll
                for (int q = 0; q < 4; q++) acc[i][j][q] = 0.f;

        load_chunk(smb, tid, 0, t, pp, mb, nb);
        load_chunk(smb, tid, 1, t, pp, mb, nb);

        for (int c = 0; c < CPT; c++) {
            CP_WAIT1();
            __syncthreads();

            uint32_t sAh = smb + (c % NSTAGE) * STAGE_BYTES;
            uint32_t sBh = sAh + TILE_BYTES;
            uint32_t sBl = sAh + 2 * TILE_BYTES;
#pragma unroll
            for (int kb = 0; kb < 4; kb++) {
                const uint32_t acsw = (uint32_t)((((2 * kb + a_ghalf) ^ a_row0) & 7) << 4);
                const uint32_t bcsw = (uint32_t)((((2 * kb + b_ghalf) ^ b_row0) & 7) << 4);
                const uint32_t brow = (uint32_t)b_row0 * 128 + bcsw;

                uint32_t ah[4][4], bh[8], bl[8];
#pragma unroll
                for (int mi = 0; mi < 4; mi++) {
                    uint32_t ad = sAh + (uint32_t)(a_row0 + mi * 16) * 128 + acsw;
                    LDMX4(ah[mi][0], ah[mi][1], ah[mi][2], ah[mi][3], ad);
                }
                LDMX4(bh[0], bh[1], bh[2], bh[3], sBh + brow);
                LDMX4(bh[4], bh[5], bh[6], bh[7], sBh + brow + 2048);
                LDMX4(bl[0], bl[1], bl[2], bl[3], sBl + brow);
                LDMX4(bl[4], bl[5], bl[6], bl[7], sBl + brow + 2048);
#pragma unroll
                for (int ni = 0; ni < 4; ni++)
#pragma unroll
                    for (int mi = 0; mi < 4; mi++) {
                        MMA16816(acc[mi][ni], ah[mi], bh[ni * 2], bh[ni * 2 + 1]);
                        MMA16816(acc[mi][ni], ah[mi], bl[ni * 2], bl[ni * 2 + 1]);
                    }
            }
            __syncthreads();
            load_chunk(smb, tid, c + NSTAGE, t, pp, mb, nb);
        }
        // drain remaining cp.async groups so next task's loads are clean
        asm volatile("cp.async.wait_group 0;" ::: "memory");

        // ---- fused LSTM cell epilogue (L1-bypass: cross-SM step handoff) ----
        const int o0 = nb * 32 + (wid & 3) * 8 + (lane & 3) * 2;
        const int chunk = nb >> 1;
        const int kk0 = o0 & 63;
        const int last = (t == TT - 1);
        float bi0 = bias[o0],            bi1 = bias[o0 + 1];
        float bf0 = bias[HDIM + o0],     bf1 = bias[HDIM + o0 + 1];
        float bg0 = bias[2*HDIM + o0],   bg1 = bias[2*HDIM + o0 + 1];
        float bo0 = bias[3*HDIM + o0],   bo1 = bias[3*HDIM + o0 + 1];
        char* th = (char*)&g_Ah[pp ^ 1][mb][chunk][0];

#pragma unroll
        for (int mi = 0; mi < 4; mi++) {
#pragma unroll
            for (int b2 = 0; b2 < 2; b2++) {
                int mrow = mw + mi * 16 + r4 + b2 * 8;
                int m = mb * 128 + mrow;
                size_t cidx = (size_t)m * HDIM + o0;
                float2 cold = __ldcg((const float2*)&g_c[cidx]);
                float gi0 = acc[mi][0][b2 * 2],     gi1 = acc[mi][0][b2 * 2 + 1];
                float gf0 = acc[mi][1][b2 * 2],     gf1 = acc[mi][1][b2 * 2 + 1];
                float gg0 = acc[mi][2][b2 * 2],     gg1 = acc[mi][2][b2 * 2 + 1];
                float go0 = acc[mi][3][b2 * 2],     go1 = acc[mi][3][b2 * 2 + 1];
                float cn0 = sigmoidf_(gf0 + bf0) * cold.x
                          + sigmoidf_(gi0 + bi0) * tanhf(gg0 + bg0);
                float cn1 = sigmoidf_(gf1 + bf1) * cold.y
                          + sigmoidf_(gi1 + bi1) * tanhf(gg1 + bg1);
                float h0 = sigmoidf_(go0 + bo0) * tanhf(cn0);
                float h1 = sigmoidf_(go1 + bo1) * tanhf(cn1);
                __stcg((float2*)&g_c[cidx], make_float2(cn0, cn1));
                if (last) *(float2*)&g_hf[cidx] = make_float2(h0, h1);
                uint32_t hv = hpack(h0, h1);
                asm volatile("st.global.cg.u32 [%0], %1;"
                             :: "l"(th + aoff(mrow, kk0)), "r"(hv) : "memory");
            }
        }

        // publish completion
        __threadfence();
        __syncthreads();
        if (tid == 0) atomicAdd(&g_dep[t][mb], 1u);
    }
}

// ---------------------------------------------------------------------------
// Key pass (batch 8): reads prepped fp16 hi+lo W tiles (17.8MB vs 68MB f32)
// ---------------------------------------------------------------------------
__global__ void key_gemm(const float* __restrict__ key, int t, int p)
{
    __shared__ float hs[KBATCH][KC];
    const int cb = blockIdx.x;   // 16 col-blocks of 256
    const int ks = blockIdx.y;   // 17 chunks
    const int tid = threadIdx.x;

    for (int i = tid; i < KBATCH * KC; i += 256) {
        int mm = i >> 6, kk = i & 63;
        float v = 0.f;
        if (ks < 16) v = g_hk[p][mm * HDIM + ks * KC + kk];
        else if (kk < DD) v = key[(size_t)(mm * TT + t) * DD + kk];
        hs[mm][kk] = v;
    }
    __syncthreads();

    const int col = cb * 256 + tid;
    const int gate = col >> 10, c10 = col & 1023;
    const int nbb = c10 >> 5, w2 = (c10 >> 3) & 3, ol = c10 & 7;
    const int n = w2 * 32 + gate * 8 + ol;
    const char* th = (const char*)&g_Wh[nbb][ks][0] + n * 128;
    const char* tl = (const char*)&g_Wl[nbb][ks][0] + n * 128;

    float acc[KBATCH];
#pragma unroll
    for (int mm = 0; mm < KBATCH; mm++) acc[mm] = 0.f;

#pragma unroll
    for (int g = 0; g < 8; g++) {
        uint32_t off = (uint32_t)(((g ^ n) & 7) << 4);
        uint4 vh = *(const uint4*)(th + off);
        uint4 vl = *(const uint4*)(tl + off);
        const __half2* ph = (const __half2*)&vh;
        const __half2* pl = (const __half2*)&vl;
#pragma unroll
        for (int j = 0; j < 4; j++) {
            float2 fh = __half22float2(ph[j]);
            float2 fl = __half22float2(pl[j]);
            float w0 = fh.x + fl.x, w1 = fh.y + fl.y;
            int k0 = g * 8 + j * 2;
#pragma unroll
            for (int mm = 0; mm < KBATCH; mm++)
                acc[mm] += hs[mm][k0] * w0 + hs[mm][k0 + 1] * w1;
        }
    }
#pragma unroll
    for (int mm = 0; mm < KBATCH; mm++)
        atomicAdd(&g_gk[mm][col], acc[mm]);
}

__global__ void key_cell(const float* __restrict__ bias, int p)
{
    int i = blockIdx.x * blockDim.x + threadIdx.x;
    if (i >= KBATCH * HDIM) return;
    int mm = i >> 10, n = i & (HDIM - 1);
    float gi = g_gk[mm][n] + bias[n];
    float gf = g_gk[mm][HDIM + n] + bias[HDIM + n];
    float gg = g_gk[mm][2 * HDIM + n] + bias[2 * HDIM + n];
    float go = g_gk[mm][3 * HDIM + n] + bias[3 * HDIM + n];
    g_gk[mm][n] = 0.f; g_gk[mm][HDIM + n] = 0.f;
    g_gk[mm][2 * HDIM + n] = 0.f; g_gk[mm][3 * HDIM + n] = 0.f;
    float cold = g_ck[mm * HDIM + n];
    float cn = sigmoidf_(gf) * cold + sigmoidf_(gi) * tanhf(gg);
    g_ck[mm * HDIM + n] = cn;
    g_hk[1 - p][mm * HDIM + n] = sigmoidf_(go) * tanhf(cn);
}

__global__ void key_init()
{
    int i = blockIdx.x * blockDim.x + threadIdx.x;
    if (i < KBATCH * HDIM) { g_hk[0][i] = 0.f; g_ck[i] = 0.f; }
    if (i < KBATCH * GDIM) g_gk[i / GDIM][i % GDIM] = 0.f;
    if (i == 0) g_ticket = 0u;
    if (i < TT * MBK) g_dep[i / MBK][i % MBK] = 0u;
}

__global__ void key_mean(int p)
{
    int n = blockIdx.x * blockDim.x + threadIdx.x;
    if (n < HDIM) {
        float sh = 0.f, sc = 0.f;
        for (int m = 0; m < KBATCH; m++) {
            sh += g_hk[p][m * HDIM + n];
            sc += g_ck[m * HDIM + n];
        }
        g_h0[n] = sh * (1.0f / KBATCH);
        g_c0[n] = sc * (1.0f / KBATCH);
    }
}

// broadcast h0/c0 into A tiles + c
__global__ void bcast_init()
{
    int mb = blockIdx.x, ch = blockIdx.y;
    int r = threadIdx.x;
    int m = mb * 128 + r;
    char* th = (char*)&g_Ah[0][mb][ch][0];
#pragma unroll
    for (int kk = 0; kk < KC; kk += 2) {
        int n = ch * KC + kk;
        float v0 = g_h0[n], v1 = g_h0[n + 1];
        *(uint32_t*)(th + aoff(r, kk)) = hpack(v0, v1);
        *(float2*)&g_c[(size_t)m * HDIM + n] = make_float2(g_c0[n], g_c0[n + 1]);
    }
}

// ---------------------------------------------------------------------------
__global__ void classify(const float* __restrict__ Wcls,
                         const float* __restrict__ bcls,
                         float* __restrict__ out)
{
    int gw = (blockIdx.x * blockDim.x + threadIdx.x) >> 5;
    int lane = threadIdx.x & 31;
    if (gw >= BB) return;
    const float* hr = &g_hf[(size_t)gw * HDIM];
    float acc[10];
#pragma unroll
    for (int c = 0; c < 10; c++) acc[c] = 0.f;
    for (int k = lane; k < HDIM; k += 32) {
        float hv = hr[k];
#pragma unroll
        for (int c = 0; c < 10; c++) acc[c] += hv * Wcls[k * 10 + c];
    }
#pragma unroll
    for (int c = 0; c < 10; c++) {
#pragma unroll
        for (int off = 16; off > 0; off >>= 1)
            acc[c] += __shfl_down_sync(0xffffffffu, acc[c], off);
    }
    if (lane == 0) {
#pragma unroll
        for (int c = 0; c < 10; c++)
            out[(size_t)gw * 10 + c] = acc[c] + bcls[c];
    }
}

// ---------------------------------------------------------------------------
extern "C" void kernel_launch(void* const* d_in, const int* in_sizes, int n_in,
                              void* d_out, int out_size)
{
    const float* x    = (const float*)d_in[0];
    const float* key  = (const float*)d_in[1];
    const float* Wih  = (const float*)d_in[2];
    const float* Whh  = (const float*)d_in[3];
    const float* b    = (const float*)d_in[4];
    const float* Wcls = (const float*)d_in[5];
    const float* bcls = (const float*)d_in[6];
    float* out = (float*)d_out;

    cudaFuncSetAttribute(data_persist, cudaFuncAttributeMaxDynamicSharedMemorySize,
                         SMEM_DATA);

    prep_W<<<dim3(CPT, NBK), 256>>>(Wih, Whh);
    prep_x<<<dim3(MBK, TT), 128>>>(x);

    key_init<<<(KBATCH * GDIM + 255) / 256, 256>>>();
    for (int t = 0; t < TT; t++) {
        key_gemm<<<dim3(GDIM / 256, CPT), 256>>>(key, t, t & 1);
        key_cell<<<(KBATCH * HDIM + 255) / 256, 256>>>(b, t & 1);
    }
    key_mean<<<(HDIM + 255) / 256, 256>>>(0);
    bcast_init<<<dim3(MBK, 16), 128>>>();

    // Data pass: single persistent kernel, device-side scheduling
    data_persist<<<PGRID, 256, SMEM_DATA>>>(b);

    classify<<<BB / 8, 256>>>(Wcls, bcls, out);
}

// round 14
// speedup vs baseline: 1.4929x; 1.0016x over previous
#include <cuda_runtime.h>
#include <cuda_fp16.h>
#include <cstdint>
#include <math.h>

#define HDIM 1024
#define GDIM 4096
#define TT 28
#define DD 28
#define BB 4096
#define KBATCH 8

// GEMM: C[4096 x 4096gates], fp16 2-term (AhBh + AhBl), per-K-chunk fused
// CTA tile 128m x 128n, warp tile 64x32, NSTAGE=2 -> 96KB smem -> 2 CTA/SM
// Data pass = ONE persistent kernel (device ticket scheduler, per-(t,mb) deps)
// Key pass  = ONE persistent kernel (272 CTAs, grid barriers, L2-warm weights)
#define KC 64
#define CPT 17            // K-chunks (16 h-chunks + 1 x-chunk)
#define NSTAGE 2
#define TILE_BYTES 16384  // 128 x 64 fp16
#define STAGE_BYTES 49152 // Ah + Bh + Bl
#define SMEM_DATA (NSTAGE * STAGE_BYTES)   // 96 KB
#define MBK 32            // 4096/128 M-blocks
#define NBK 32            // 1024/32 out-blocks (128 gate-cols per CTA)
#define NTASK (TT * MBK * NBK)
#define PGRID 296         // 2 CTAs x 148 SMs, all resident
#define KGRID 272         // key pass: 16 col-blocks x 17 chunks, all resident

// ---------------- persistent scratch ----------------
__device__ __half g_Wh[NBK][CPT][8192];
__device__ __half g_Wl[NBK][CPT][8192];
__device__ __half g_Ah[2][MBK][16][8192];   // h tiles (fp16 rounded), ping-pong
__device__ __half g_xh[TT][MBK][8192];
__device__ float g_c[(size_t)BB * HDIM];
__device__ float g_hf[(size_t)BB * HDIM];
__device__ float g_hk[2][KBATCH * HDIM];
__device__ float g_ck[KBATCH * HDIM];
__device__ float g_gk[KBATCH][GDIM];
__device__ float g_h0[HDIM];
__device__ float g_c0[HDIM];
__device__ unsigned int g_ticket;
__device__ unsigned int g_dep[TT][MBK];
__device__ unsigned int g_kbar;

// ---------------- helpers ----------------
__device__ __forceinline__ float sigmoidf_(float x) { return 1.0f / (1.0f + __expf(-x)); }

// swizzled byte offset within a [rows x 64] fp16 tile (128B rows, 16B groups)
__device__ __forceinline__ uint32_t aoff(int row, int kk) {
    return (uint32_t)(row * 128 + ((((kk >> 3) ^ row) & 7) << 4) + (kk & 7) * 2);
}

__device__ __forceinline__ uint32_t smem_u32(const void* p) {
    uint32_t a;
    asm("{ .reg .u64 t; cvta.to.shared.u64 t, %1; cvt.u32.u64 %0, t; }" : "=r"(a) : "l"(p));
    return a;
}

__device__ __forceinline__ uint32_t hpack(float v0, float v1) {
    __half2 p = __floats2half2_rn(v0, v1);
    return *(uint32_t*)&p;
}

#define CP_ASYNC16(dst, src) \
    asm volatile("cp.async.cg.shared.global [%0], [%1], 16;" :: "r"(dst), "l"(src))
#define CP_COMMIT() asm volatile("cp.async.commit_group;" ::: "memory")
#define CP_WAIT1() asm volatile("cp.async.wait_group 1;" ::: "memory")

#define LDMX4(r0, r1, r2, r3, addr) \
    asm volatile("ldmatrix.sync.aligned.m8n8.x4.shared.b16 {%0,%1,%2,%3}, [%4];" \
        : "=r"(r0), "=r"(r1), "=r"(r2), "=r"(r3) : "r"(addr))
#define MMA16816(d, a, b0, b1) \
    asm volatile("mma.sync.aligned.m16n8k16.row.col.f32.f16.f16.f32 " \
        "{%0,%1,%2,%3},{%4,%5,%6,%7},{%8,%9},{%0,%1,%2,%3};" \
        : "+f"((d)[0]), "+f"((d)[1]), "+f"((d)[2]), "+f"((d)[3]) \
        : "r"((a)[0]), "r"((a)[1]), "r"((a)[2]), "r"((a)[3]), "r"(b0), "r"(b1))

// ---------------------------------------------------------------------------
// prep: fp16 hi/lo split of weights into swizzled [n][k] tiles.
// B tile row layout (128): warp w (n>>5), gate ((n>>3)&3), out_local (n&7)
// -> W column = gate*1024 + nb*32 + w*8 + ol ; tile row n = w*32+gate*8+ol
// ---------------------------------------------------------------------------
__global__ void prep_W(const float* __restrict__ Wih, const float* __restrict__ Whh)
{
    int kc = blockIdx.x, nb = blockIdx.y;
    int n = threadIdx.x & 127, kh = threadIdx.x >> 7;
    int w = n >> 5, gate = (n >> 3) & 3, ol = n & 7;
    int col = gate * HDIM + nb * 32 + w * 8 + ol;
    char* th = (char*)&g_Wh[nb][kc][0];
    char* tl = (char*)&g_Wl[nb][kc][0];
#pragma unroll
    for (int kk = kh * 32; kk < kh * 32 + 32; kk += 2) {
        float v0, v1;
        if (kc < 16) {
            size_t kg = (size_t)(kc * 64 + kk);
            v0 = Whh[kg * GDIM + col];
            v1 = Whh[(kg + 1) * GDIM + col];
        } else {
            v0 = (kk < DD) ? Wih[(size_t)kk * GDIM + col] : 0.f;
            v1 = (kk + 1 < DD) ? Wih[(size_t)(kk + 1) * GDIM + col] : 0.f;
        }
        float h0 = __half2float(__float2half_rn(v0));
        float h1 = __half2float(__float2half_rn(v1));
        uint32_t off = aoff(n, kk);
        *(uint32_t*)(th + off) = hpack(h0, h1);
        *(uint32_t*)(tl + off) = hpack(v0 - h0, v1 - h1);
    }
}

__global__ void prep_x(const float* __restrict__ x)
{
    int mb = blockIdx.x, t = blockIdx.y;
    int r = threadIdx.x;
    int m = mb * 128 + r;
    char* th = (char*)&g_xh[t][mb][0];
#pragma unroll
    for (int kk = 0; kk < KC; kk += 2) {
        float v0 = (kk < DD) ? x[((size_t)m * TT + t) * DD + kk] : 0.f;
        float v1 = (kk + 1 < DD) ? x[((size_t)m * TT + t) * DD + kk + 1] : 0.f;
        *(uint32_t*)(th + aoff(r, kk)) = hpack(v0, v1);
    }
}

// ---------------------------------------------------------------------------
// Persistent data pass: device-side scheduler + fp16 GEMM + fused LSTM cell
// ---------------------------------------------------------------------------
__device__ __forceinline__ void load_chunk(uint32_t smb, int tid, int c,
                                           int t, int pp, int mb, int nb)
{
    if (c < CPT) {
        const char* ah = (c == 16) ? (const char*)&g_xh[t][mb][0]
                                   : (const char*)&g_Ah[pp][mb][c][0];
        const char* bh = (const char*)&g_Wh[nb][c][0];
        const char* bl = (const char*)&g_Wl[nb][c][0];
        uint32_t dst = smb + (c % NSTAGE) * STAGE_BYTES;
        int o = tid * 16;
#pragma unroll
        for (int i = 0; i < 4; i++) {
            CP_ASYNC16(dst + o,                 ah + o);
            CP_ASYNC16(dst + TILE_BYTES + o,    bh + o);
            CP_ASYNC16(dst + 2*TILE_BYTES + o,  bl + o);
            o += 4096;
        }
    }
    CP_COMMIT();
}

__global__ void __launch_bounds__(256, 2)
data_persist(const float* __restrict__ bias)
{
    extern __shared__ __align__(128) char sm[];
    const uint32_t smb = smem_u32(sm);
    __shared__ unsigned int s_task;
    const int tid = threadIdx.x, wid = tid >> 5, lane = tid & 31;
    const int mw = (wid >> 2) * 64;       // warp m offset
    const int nw = (wid & 3) * 32;        // warp n(col) offset

    // lane geometry (task-invariant)
    const int a_row0 = mw + ((lane >> 3) & 1) * 8 + (lane & 7);   // + mi*16
    const int a_ghalf = lane >> 4;
    const int b_row0 = nw + ((lane >> 4) & 1) * 8 + (lane & 7);   // + 16 for ni 2,3
    const int b_ghalf = (lane >> 3) & 1;
    const int r4 = lane >> 2;

    for (;;) {
        if (tid == 0) s_task = atomicAdd(&g_ticket, 1u);
        __syncthreads();
        const unsigned int task = s_task;
        if (task >= NTASK) return;
        const int t  = task >> 10;
        const int mb = (task >> 5) & 31;
        const int nb = task & 31;
        const int pp = t & 1;

        // wait for step t-1 of this mb chain
        if (t > 0 && tid == 0) {
            const unsigned int* dp = &g_dep[t - 1][mb];
            unsigned int v;
            for (;;) {
                asm volatile("ld.acquire.gpu.global.u32 %0, [%1];" : "=r"(v) : "l"(dp));
                if (v >= NBK) break;
                __nanosleep(128);
            }
        }
        __syncthreads();

        float acc[4][4][4];
#pragma unroll
        for (int i = 0; i < 4; i++)
#pragma unroll
            for (int j = 0; j < 4; j++)
#pragma unroll
                for (int q = 0; q < 4; q++) acc[i][j][q] = 0.f;

        load_chunk(smb, tid, 0, t, pp, mb, nb);
        load_chunk(smb, tid, 1, t, pp, mb, nb);

        for (int c = 0; c < CPT; c++) {
            CP_WAIT1();
            __syncthreads();

            uint32_t sAh = smb + (c % NSTAGE) * STAGE_BYTES;
            uint32_t sBh = sAh + TILE_BYTES;
            uint32_t sBl = sAh + 2 * TILE_BYTES;
#pragma unroll
            for (int kb = 0; kb < 4; kb++) {
                const uint32_t acsw = (uint32_t)((((2 * kb + a_ghalf) ^ a_row0) & 7) << 4);
                const uint32_t bcsw = (uint32_t)((((2 * kb + b_ghalf) ^ b_row0) & 7) << 4);
                const uint32_t brow = (uint32_t)b_row0 * 128 + bcsw;

                uint32_t ah[4][4], bh[8], bl[8];
#pragma unroll
                for (int mi = 0; mi < 4; mi++) {
                    uint32_t ad = sAh + (uint32_t)(a_row0 + mi * 16) * 128 + acsw;
                    LDMX4(ah[mi][0], ah[mi][1], ah[mi][2], ah[mi][3], ad);
                }
                LDMX4(bh[0], bh[1], bh[2], bh[3], sBh + brow);
                LDMX4(bh[4], bh[5], bh[6], bh[7], sBh + brow + 2048);
                LDMX4(bl[0], bl[1], bl[2], bl[3], sBl + brow);
                LDMX4(bl[4], bl[5], bl[6], bl[7], sBl + brow + 2048);
#pragma unroll
                for (int ni = 0; ni < 4; ni++)
#pragma unroll
                    for (int mi = 0; mi < 4; mi++) {
                        MMA16816(acc[mi][ni], ah[mi], bh[ni * 2], bh[ni * 2 + 1]);
                        MMA16816(acc[mi][ni], ah[mi], bl[ni * 2], bl[ni * 2 + 1]);
                    }
            }
            __syncthreads();
            load_chunk(smb, tid, c + NSTAGE, t, pp, mb, nb);
        }
        // drain remaining cp.async groups so next task's loads are clean
        asm volatile("cp.async.wait_group 0;" ::: "memory");

        // ---- fused LSTM cell epilogue (L1-bypass: cross-SM step handoff) ----
        const int o0 = nb * 32 + (wid & 3) * 8 + (lane & 3) * 2;
        const int chunk = nb >> 1;
        const int kk0 = o0 & 63;
        const int last = (t == TT - 1);
        float bi0 = bias[o0],            bi1 = bias[o0 + 1];
        float bf0 = bias[HDIM + o0],     bf1 = bias[HDIM + o0 + 1];
        float bg0 = bias[2*HDIM + o0],   bg1 = bias[2*HDIM + o0 + 1];
        float bo0 = bias[3*HDIM + o0],   bo1 = bias[3*HDIM + o0 + 1];
        char* th = (char*)&g_Ah[pp ^ 1][mb][chunk][0];

#pragma unroll
        for (int mi = 0; mi < 4; mi++) {
#pragma unroll
            for (int b2 = 0; b2 < 2; b2++) {
                int mrow = mw + mi * 16 + r4 + b2 * 8;
                int m = mb * 128 + mrow;
                size_t cidx = (size_t)m * HDIM + o0;
                float2 cold = __ldcg((const float2*)&g_c[cidx]);
                float gi0 = acc[mi][0][b2 * 2],     gi1 = acc[mi][0][b2 * 2 + 1];
                float gf0 = acc[mi][1][b2 * 2],     gf1 = acc[mi][1][b2 * 2 + 1];
                float gg0 = acc[mi][2][b2 * 2],     gg1 = acc[mi][2][b2 * 2 + 1];
                float go0 = acc[mi][3][b2 * 2],     go1 = acc[mi][3][b2 * 2 + 1];
                float cn0 = sigmoidf_(gf0 + bf0) * cold.x
                          + sigmoidf_(gi0 + bi0) * tanhf(gg0 + bg0);
                float cn1 = sigmoidf_(gf1 + bf1) * cold.y
                          + sigmoidf_(gi1 + bi1) * tanhf(gg1 + bg1);
                float h0 = sigmoidf_(go0 + bo0) * tanhf(cn0);
                float h1 = sigmoidf_(go1 + bo1) * tanhf(cn1);
                __stcg((float2*)&g_c[cidx], make_float2(cn0, cn1));
                if (last) *(float2*)&g_hf[cidx] = make_float2(h0, h1);
                uint32_t hv = hpack(h0, h1);
                asm volatile("st.global.cg.u32 [%0], %1;"
                             :: "l"(th + aoff(mrow, kk0)), "r"(hv) : "memory");
            }
        }

        // publish completion
        __threadfence();
        __syncthreads();
        if (tid == 0) atomicAdd(&g_dep[t][mb], 1u);
    }
}

// ---------------------------------------------------------------------------
// Persistent key pass: 272 CTAs, 28 steps in-device, 2 grid barriers/step
// ---------------------------------------------------------------------------
__device__ __forceinline__ void grid_bar(unsigned int* phase)
{
    __syncthreads();
    if (threadIdx.x == 0) {
        __threadfence();
        atomicAdd(&g_kbar, 1u);
        unsigned int target = *phase + KGRID;
        unsigned int v;
        for (;;) {
            asm volatile("ld.acquire.gpu.global.u32 %0, [%1];" : "=r"(v) : "l"(&g_kbar));
            if (v >= target) break;
            __nanosleep(64);
        }
    }
    *phase += KGRID;
    __syncthreads();
}

__global__ void __launch_bounds__(256, 2)
key_persist(const float* __restrict__ key, const float* __restrict__ bias)
{
    __shared__ float hs[KBATCH][KC];
    const int bid = blockIdx.x;
    const int cb = bid & 15;      // col block 0..15
    const int ks = bid >> 4;      // chunk 0..16
    const int tid = threadIdx.x;

    const int col = cb * 256 + tid;
    const int gate = col >> 10, c10 = col & 1023;
    const int nbb = c10 >> 5, w2 = (c10 >> 3) & 3, ol = c10 & 7;
    const int n = w2 * 32 + gate * 8 + ol;
    const char* th = (const char*)&g_Wh[nbb][ks][0] + n * 128;
    const char* tl = (const char*)&g_Wl[nbb][ks][0] + n * 128;

    unsigned int phase = 0;

    for (int t = 0; t < TT; t++) {
        const int p = t & 1;
        // stage h (or x for the tail chunk) into shared
        for (int i = tid; i < KBATCH * KC; i += 256) {
            int mm = i >> 6, kk = i & 63;
            float v = 0.f;
            if (ks < 16) v = __ldcg(&g_hk[p][mm * HDIM + ks * KC + kk]);
            else if (kk < DD) v = key[(size_t)(mm * TT + t) * DD + kk];
            hs[mm][kk] = v;
        }
        __syncthreads();

        float acc[KBATCH];
#pragma unroll
        for (int mm = 0; mm < KBATCH; mm++) acc[mm] = 0.f;

#pragma unroll
        for (int g = 0; g < 8; g++) {
            uint32_t off = (uint32_t)(((g ^ n) & 7) << 4);
            uint4 vh = *(const uint4*)(th + off);
            uint4 vl = *(const uint4*)(tl + off);
            const __half2* ph = (const __half2*)&vh;
            const __half2* pl = (const __half2*)&vl;
#pragma unroll
            for (int j = 0; j < 4; j++) {
                float2 fh = __half22float2(ph[j]);
                float2 fl = __half22float2(pl[j]);
                float w0 = fh.x + fl.x, w1 = fh.y + fl.y;
                int k0 = g * 8 + j * 2;
#pragma unroll
                for (int mm = 0; mm < KBATCH; mm++)
                    acc[mm] += hs[mm][k0] * w0 + hs[mm][k0 + 1] * w1;
            }
        }
#pragma unroll
        for (int mm = 0; mm < KBATCH; mm++)
            atomicAdd(&g_gk[mm][col], acc[mm]);

        grid_bar(&phase);   // all gate adds complete

        // cell update: first 32 CTAs cover 8192 (mm,n) pairs
        if (bid < 32) {
            int i = bid * 256 + tid;
            int mm = i >> 10, nn = i & (HDIM - 1);
            float gi = __ldcg(&g_gk[mm][nn]) + bias[nn];
            float gf = __ldcg(&g_gk[mm][HDIM + nn]) + bias[HDIM + nn];
            float gg = __ldcg(&g_gk[mm][2 * HDIM + nn]) + bias[2 * HDIM + nn];
            float go = __ldcg(&g_gk[mm][3 * HDIM + nn]) + bias[3 * HDIM + nn];
            __stcg(&g_gk[mm][nn], 0.f);
            __stcg(&g_gk[mm][HDIM + nn], 0.f);
            __stcg(&g_gk[mm][2 * HDIM + nn], 0.f);
            __stcg(&g_gk[mm][3 * HDIM + nn], 0.f);
            float cold = g_ck[mm * HDIM + nn];
            float cn = sigmoidf_(gf) * cold + sigmoidf_(gi) * tanhf(gg);
            g_ck[mm * HDIM + nn] = cn;
            __stcg(&g_hk[1 - p][mm * HDIM + nn], sigmoidf_(go) * tanhf(cn));
        }

        grid_bar(&phase);   // h/c published, g_gk cleared
    }
}

__global__ void key_init()
{
    int i = blockIdx.x * blockDim.x + threadIdx.x;
    if (i < KBATCH * HDIM) { g_hk[0][i] = 0.f; g_ck[i] = 0.f; }
    if (i < KBATCH * GDIM) g_gk[i / GDIM][i % GDIM] = 0.f;
    if (i == 0) { g_ticket = 0u; g_kbar = 0u; }
    if (i < TT * MBK) g_dep[i / MBK][i % MBK] = 0u;
}

__global__ void key_mean(int p)
{
    int n = blockIdx.x * blockDim.x + threadIdx.x;
    if (n < HDIM) {
        float sh = 0.f, sc = 0.f;
        for (int m = 0; m < KBATCH; m++) {
            sh += g_hk[p][m * HDIM + n];
            sc += g_ck[m * HDIM + n];
        }
        g_h0[n] = sh * (1.0f / KBATCH);
        g_c0[n] = sc * (1.0f / KBATCH);
    }
}

// broadcast h0/c0 into A tiles + c
__global__ void bcast_init()
{
    int mb = blockIdx.x, ch = blockIdx.y;
    int r = threadIdx.x;
    int m = mb * 128 + r;
    char* th = (char*)&g_Ah[0][mb][ch][0];
#pragma unroll
    for (int kk = 0; kk < KC; kk += 2) {
        int n = ch * KC + kk;
        float v0 = g_h0[n], v1 = g_h0[n + 1];
        *(uint32_t*)(th + aoff(r, kk)) = hpack(v0, v1);
        *(float2*)&g_c[(size_t)m * HDIM + n] = make_float2(g_c0[n], g_c0[n + 1]);
    }
}

// ---------------------------------------------------------------------------
__global__ void classify(const float* __restrict__ Wcls,
                         const float* __restrict__ bcls,
                         float* __restrict__ out)
{
    int gw = (blockIdx.x * blockDim.x + threadIdx.x) >> 5;
    int lane = threadIdx.x & 31;
    if (gw >= BB) return;
    const float* hr = &g_hf[(size_t)gw * HDIM];
    float acc[10];
#pragma unroll
    for (int c = 0; c < 10; c++) acc[c] = 0.f;
    for (int k = lane; k < HDIM; k += 32) {
        float hv = hr[k];
#pragma unroll
        for (int c = 0; c < 10; c++) acc[c] += hv * Wcls[k * 10 + c];
    }
#pragma unroll
    for (int c = 0; c < 10; c++) {
#pragma unroll
        for (int off = 16; off > 0; off >>= 1)
            acc[c] += __shfl_down_sync(0xffffffffu, acc[c], off);
    }
    if (lane == 0) {
#pragma unroll
        for (int c = 0; c < 10; c++)
            out[(size_t)gw * 10 + c] = acc[c] + bcls[c];
    }
}

// ---------------------------------------------------------------------------
extern "C" void kernel_launch(void* const* d_in, const int* in_sizes, int n_in,
                              void* d_out, int out_size)
{
    const float* x    = (const float*)d_in[0];
    const float* key  = (const float*)d_in[1];
    const float* Wih  = (const float*)d_in[2];
    const float* Whh  = (const float*)d_in[3];
    const float* b    = (const float*)d_in[4];
    const float* Wcls = (const float*)d_in[5];
    const float* bcls = (const float*)d_in[6];
    float* out = (float*)d_out;

    cudaFuncSetAttribute(data_persist, cudaFuncAttributeMaxDynamicSharedMemorySize,
                         SMEM_DATA);

    prep_W<<<dim3(CPT, NBK), 256>>>(Wih, Whh);
    prep_x<<<dim3(MBK, TT), 128>>>(x);

    key_init<<<(KBATCH * GDIM + 255) / 256, 256>>>();
    key_persist<<<KGRID, 256>>>(key, b);
    key_mean<<<(HDIM + 255) / 256, 256>>>(0);
    bcast_init<<<dim3(MBK, 16), 128>>>();

    // Data pass: single persistent kernel, device-side scheduling
    data_persist<<<PGRID, 256, SMEM_DATA>>>(b);

    classify<<<BB / 8, 256>>>(Wcls, bcls, out);
}

// round 15
// speedup vs baseline: 2.3204x; 1.5543x over previous
#include <cuda_runtime.h>
#include <cuda_fp16.h>
#include <cstdint>
#include <math.h>

#define HDIM 1024
#define GDIM 4096
#define TT 28
#define DD 28
#define BB 4096
#define KBATCH 8

// GEMM: C[4096 x 4096gates], SINGLE fp16 term (A_fp16 x W_fp16), per-K-chunk
// CTA tile 128m x 128n, warp tile 64x32, NSTAGE=3 x 32KB -> 96KB -> 2 CTA/SM
// Data pass = ONE persistent kernel (device ticket scheduler, per-(t,mb) deps)
// Key pass  = ONE persistent kernel (272 CTAs, grid barriers, exact W hi+lo)
#define KC 64
#define CPT 17            // K-chunks (16 h-chunks + 1 x-chunk)
#define NSTAGE 3
#define TILE_BYTES 16384  // 128 x 64 fp16
#define STAGE_BYTES 32768 // Ah + Bh
#define SMEM_DATA (NSTAGE * STAGE_BYTES)   // 96 KB
#define MBK 32            // 4096/128 M-blocks
#define NBK 32            // 1024/32 out-blocks (128 gate-cols per CTA)
#define NTASK (TT * MBK * NBK)
#define PGRID 296         // 2 CTAs x 148 SMs, all resident
#define KGRID 272         // key pass: 16 col-blocks x 17 chunks, all resident

// ---------------- persistent scratch ----------------
__device__ __half g_Wh[NBK][CPT][8192];
__device__ __half g_Wl[NBK][CPT][8192];
__device__ __half g_Ah[2][MBK][16][8192];   // h tiles (fp16 rounded), ping-pong
__device__ __half g_xh[TT][MBK][8192];
__device__ float g_c[(size_t)BB * HDIM];
__device__ float g_hf[(size_t)BB * HDIM];
__device__ float g_hk[2][KBATCH * HDIM];
__device__ float g_ck[KBATCH * HDIM];
__device__ float g_gk[KBATCH][GDIM];
__device__ float g_h0[HDIM];
__device__ float g_c0[HDIM];
__device__ unsigned int g_ticket;
__device__ unsigned int g_dep[TT][MBK];
__device__ unsigned int g_kbar;

// ---------------- helpers ----------------
__device__ __forceinline__ float sigmoidf_(float x) { return 1.0f / (1.0f + __expf(-x)); }

// swizzled byte offset within a [rows x 64] fp16 tile (128B rows, 16B groups)
__device__ __forceinline__ uint32_t aoff(int row, int kk) {
    return (uint32_t)(row * 128 + ((((kk >> 3) ^ row) & 7) << 4) + (kk & 7) * 2);
}

__device__ __forceinline__ uint32_t smem_u32(const void* p) {
    uint32_t a;
    asm("{ .reg .u64 t; cvta.to.shared.u64 t, %1; cvt.u32.u64 %0, t; }" : "=r"(a) : "l"(p));
    return a;
}

__device__ __forceinline__ uint32_t hpack(float v0, float v1) {
    __half2 p = __floats2half2_rn(v0, v1);
    return *(uint32_t*)&p;
}

#define CP_ASYNC16(dst, src) \
    asm volatile("cp.async.cg.shared.global [%0], [%1], 16;" :: "r"(dst), "l"(src))
#define CP_COMMIT() asm volatile("cp.async.commit_group;" ::: "memory")
#define CP_WAIT2() asm volatile("cp.async.wait_group 2;" ::: "memory")

#define LDMX4(r0, r1, r2, r3, addr) \
    asm volatile("ldmatrix.sync.aligned.m8n8.x4.shared.b16 {%0,%1,%2,%3}, [%4];" \
        : "=r"(r0), "=r"(r1), "=r"(r2), "=r"(r3) : "r"(addr))
#define MMA16816(d, a, b0, b1) \
    asm volatile("mma.sync.aligned.m16n8k16.row.col.f32.f16.f16.f32 " \
        "{%0,%1,%2,%3},{%4,%5,%6,%7},{%8,%9},{%0,%1,%2,%3};" \
        : "+f"((d)[0]), "+f"((d)[1]), "+f"((d)[2]), "+f"((d)[3]) \
        : "r"((a)[0]), "r"((a)[1]), "r"((a)[2]), "r"((a)[3]), "r"(b0), "r"(b1))

// ---------------------------------------------------------------------------
// prep: fp16 hi/lo split of weights into swizzled [n][k] tiles.
// B tile row layout (128): warp w (n>>5), gate ((n>>3)&3), out_local (n&7)
// -> W column = gate*1024 + nb*32 + w*8 + ol ; tile row n = w*32+gate*8+ol
// ---------------------------------------------------------------------------
__global__ void prep_W(const float* __restrict__ Wih, const float* __restrict__ Whh)
{
    int kc = blockIdx.x, nb = blockIdx.y;
    int n = threadIdx.x & 127, kh = threadIdx.x >> 7;
    int w = n >> 5, gate = (n >> 3) & 3, ol = n & 7;
    int col = gate * HDIM + nb * 32 + w * 8 + ol;
    char* th = (char*)&g_Wh[nb][kc][0];
    char* tl = (char*)&g_Wl[nb][kc][0];
#pragma unroll
    for (int kk = kh * 32; kk < kh * 32 + 32; kk += 2) {
        float v0, v1;
        if (kc < 16) {
            size_t kg = (size_t)(kc * 64 + kk);
            v0 = Whh[kg * GDIM + col];
            v1 = Whh[(kg + 1) * GDIM + col];
        } else {
            v0 = (kk < DD) ? Wih[(size_t)kk * GDIM + col] : 0.f;
            v1 = (kk + 1 < DD) ? Wih[(size_t)(kk + 1) * GDIM + col] : 0.f;
        }
        float h0 = __half2float(__float2half_rn(v0));
        float h1 = __half2float(__float2half_rn(v1));
        uint32_t off = aoff(n, kk);
        *(uint32_t*)(th + off) = hpack(h0, h1);
        *(uint32_t*)(tl + off) = hpack(v0 - h0, v1 - h1);
    }
}

__global__ void prep_x(const float* __restrict__ x)
{
    int mb = blockIdx.x, t = blockIdx.y;
    int r = threadIdx.x;
    int m = mb * 128 + r;
    char* th = (char*)&g_xh[t][mb][0];
#pragma unroll
    for (int kk = 0; kk < KC; kk += 2) {
        float v0 = (kk < DD) ? x[((size_t)m * TT + t) * DD + kk] : 0.f;
        float v1 = (kk + 1 < DD) ? x[((size_t)m * TT + t) * DD + kk + 1] : 0.f;
        *(uint32_t*)(th + aoff(r, kk)) = hpack(v0, v1);
    }
}

// ---------------------------------------------------------------------------
// Persistent data pass: device-side scheduler + fp16 GEMM + fused LSTM cell
// Stage layout: [Ah 16K][Bh 16K]
// ---------------------------------------------------------------------------
__device__ __forceinline__ void load_chunk(uint32_t smb, int tid, int c,
                                           int t, int pp, int mb, int nb)
{
    if (c < CPT) {
        const char* ah = (c == 16) ? (const char*)&g_xh[t][mb][0]
                                   : (const char*)&g_Ah[pp][mb][c][0];
        const char* bh = (const char*)&g_Wh[nb][c][0];
        uint32_t dst = smb + (c % NSTAGE) * STAGE_BYTES;
        int o = tid * 16;
#pragma unroll
        for (int i = 0; i < 4; i++) {
            CP_ASYNC16(dst + o,              ah + o);
            CP_ASYNC16(dst + TILE_BYTES + o, bh + o);
            o += 4096;
        }
    }
    CP_COMMIT();
}

__global__ void __launch_bounds__(256, 2)
data_persist(const float* __restrict__ bias)
{
    extern __shared__ __align__(128) char sm[];
    const uint32_t smb = smem_u32(sm);
    __shared__ unsigned int s_task;
    const int tid = threadIdx.x, wid = tid >> 5, lane = tid & 31;
    const int mw = (wid >> 2) * 64;       // warp m offset
    const int nw = (wid & 3) * 32;        // warp n(col) offset

    // lane geometry (task-invariant)
    const int a_row0 = mw + ((lane >> 3) & 1) * 8 + (lane & 7);   // + mi*16
    const int a_ghalf = lane >> 4;
    const int b_row0 = nw + ((lane >> 4) & 1) * 8 + (lane & 7);   // + 16 for ni 2,3
    const int b_ghalf = (lane >> 3) & 1;
    const int r4 = lane >> 2;

    for (;;) {
        if (tid == 0) s_task = atomicAdd(&g_ticket, 1u);
        __syncthreads();
        const unsigned int task = s_task;
        if (task >= NTASK) return;
        const int t  = task >> 10;
        const int mb = (task >> 5) & 31;
        const int nb = task & 31;
        const int pp = t & 1;

        // wait for step t-1 of this mb chain
        if (t > 0 && tid == 0) {
            const unsigned int* dp = &g_dep[t - 1][mb];
            unsigned int v;
            for (;;) {
                asm volatile("ld.acquire.gpu.global.u32 %0, [%1];" : "=r"(v) : "l"(dp));
                if (v >= NBK) break;
                __nanosleep(128);
            }
        }
        __syncthreads();

        float acc[4][4][4];
#pragma unroll
        for (int i = 0; i < 4; i++)
#pragma unroll
            for (int j = 0; j < 4; j++)
#pragma unroll
                for (int q = 0; q < 4; q++) acc[i][j][q] = 0.f;

        load_chunk(smb, tid, 0, t, pp, mb, nb);
        load_chunk(smb, tid, 1, t, pp, mb, nb);
        load_chunk(smb, tid, 2, t, pp, mb, nb);

        for (int c = 0; c < CPT; c++) {
            CP_WAIT2();
            __syncthreads();

            uint32_t sAh = smb + (c % NSTAGE) * STAGE_BYTES;
            uint32_t sBh = sAh + TILE_BYTES;
#pragma unroll
            for (int kb = 0; kb < 4; kb++) {
                const uint32_t acsw = (uint32_t)((((2 * kb + a_ghalf) ^ a_row0) & 7) << 4);
                const uint32_t bcsw = (uint32_t)((((2 * kb + b_ghalf) ^ b_row0) & 7) << 4);
                const uint32_t brow = (uint32_t)b_row0 * 128 + bcsw;

                uint32_t ah[4][4], bh[8];
#pragma unroll
                for (int mi = 0; mi < 4; mi++) {
                    uint32_t ad = sAh + (uint32_t)(a_row0 + mi * 16) * 128 + acsw;
                    LDMX4(ah[mi][0], ah[mi][1], ah[mi][2], ah[mi][3], ad);
                }
                LDMX4(bh[0], bh[1], bh[2], bh[3], sBh + brow);
                LDMX4(bh[4], bh[5], bh[6], bh[7], sBh + brow + 2048);
#pragma unroll
                for (int ni = 0; ni < 4; ni++)
#pragma unroll
                    for (int mi = 0; mi < 4; mi++)
                        MMA16816(acc[mi][ni], ah[mi], bh[ni * 2], bh[ni * 2 + 1]);
            }
            __syncthreads();
            load_chunk(smb, tid, c + NSTAGE, t, pp, mb, nb);
        }
        // drain remaining cp.async groups so next task's loads are clean
        asm volatile("cp.async.wait_group 0;" ::: "memory");

        // ---- fused LSTM cell epilogue (L1-bypass: cross-SM step handoff) ----
        const int o0 = nb * 32 + (wid & 3) * 8 + (lane & 3) * 2;
        const int chunk = nb >> 1;
        const int kk0 = o0 & 63;
        const int last = (t == TT - 1);
        float bi0 = bias[o0],            bi1 = bias[o0 + 1];
        float bf0 = bias[HDIM + o0],     bf1 = bias[HDIM + o0 + 1];
        float bg0 = bias[2*HDIM + o0],   bg1 = bias[2*HDIM + o0 + 1];
        float bo0 = bias[3*HDIM + o0],   bo1 = bias[3*HDIM + o0 + 1];
        char* th = (char*)&g_Ah[pp ^ 1][mb][chunk][0];

#pragma unroll
        for (int mi = 0; mi < 4; mi++) {
#pragma unroll
            for (int b2 = 0; b2 < 2; b2++) {
                int mrow = mw + mi * 16 + r4 + b2 * 8;
                int m = mb * 128 + mrow;
                size_t cidx = (size_t)m * HDIM + o0;
                float2 cold = __ldcg((const float2*)&g_c[cidx]);
                float gi0 = acc[mi][0][b2 * 2],     gi1 = acc[mi][0][b2 * 2 + 1];
                float gf0 = acc[mi][1][b2 * 2],     gf1 = acc[mi][1][b2 * 2 + 1];
                float gg0 = acc[mi][2][b2 * 2],     gg1 = acc[mi][2][b2 * 2 + 1];
                float go0 = acc[mi][3][b2 * 2],     go1 = acc[mi][3][b2 * 2 + 1];
                float cn0 = sigmoidf_(gf0 + bf0) * cold.x
                          + sigmoidf_(gi0 + bi0) * tanhf(gg0 + bg0);
                float cn1 = sigmoidf_(gf1 + bf1) * cold.y
                          + sigmoidf_(gi1 + bi1) * tanhf(gg1 + bg1);
                float h0 = sigmoidf_(go0 + bo0) * tanhf(cn0);
                float h1 = sigmoidf_(go1 + bo1) * tanhf(cn1);
                __stcg((float2*)&g_c[cidx], make_float2(cn0, cn1));
                if (last) *(float2*)&g_hf[cidx] = make_float2(h0, h1);
                uint32_t hv = hpack(h0, h1);
                asm volatile("st.global.cg.u32 [%0], %1;"
                             :: "l"(th + aoff(mrow, kk0)), "r"(hv) : "memory");
            }
        }

        // publish completion
        __threadfence();
        __syncthreads();
        if (tid == 0) atomicAdd(&g_dep[t][mb], 1u);
    }
}

// ---------------------------------------------------------------------------
// Persistent key pass: 272 CTAs, 28 steps in-device, 2 grid barriers/step
// Uses exact W (hi+lo) so the h0/c0 seed stays near-fp32 accurate.
// ---------------------------------------------------------------------------
__device__ __forceinline__ void grid_bar(unsigned int* phase)
{
    __syncthreads();
    if (threadIdx.x == 0) {
        __threadfence();
        atomicAdd(&g_kbar, 1u);
        unsigned int target = *phase + KGRID;
        unsigned int v;
        for (;;) {
            asm volatile("ld.acquire.gpu.global.u32 %0, [%1];" : "=r"(v) : "l"(&g_kbar));
            if (v >= target) break;
            __nanosleep(64);
        }
    }
    *phase += KGRID;
    __syncthreads();
}

__global__ void __launch_bounds__(256, 2)
key_persist(const float* __restrict__ key, const float* __restrict__ bias)
{
    __shared__ float hs[KBATCH][KC];
    const int bid = blockIdx.x;
    const int cb = bid & 15;      // col block 0..15
    const int ks = bid >> 4;      // chunk 0..16
    const int tid = threadIdx.x;

    const int col = cb * 256 + tid;
    const int gate = col >> 10, c10 = col & 1023;
    const int nbb = c10 >> 5, w2 = (c10 >> 3) & 3, ol = c10 & 7;
    const int n = w2 * 32 + gate * 8 + ol;
    const char* th = (const char*)&g_Wh[nbb][ks][0] + n * 128;
    const char* tl = (const char*)&g_Wl[nbb][ks][0] + n * 128;

    unsigned int phase = 0;

    for (int t = 0; t < TT; t++) {
        const int p = t & 1;
        for (int i = tid; i < KBATCH * KC; i += 256) {
            int mm = i >> 6, kk = i & 63;
            float v = 0.f;
            if (ks < 16) v = __ldcg(&g_hk[p][mm * HDIM + ks * KC + kk]);
            else if (kk < DD) v = key[(size_t)(mm * TT + t) * DD + kk];
            hs[mm][kk] = v;
        }
        __syncthreads();

        float acc[KBATCH];
#pragma unroll
        for (int mm = 0; mm < KBATCH; mm++) acc[mm] = 0.f;

#pragma unroll
        for (int g = 0; g < 8; g++) {
            uint32_t off = (uint32_t)(((g ^ n) & 7) << 4);
            uint4 vh = *(const uint4*)(th + off);
            uint4 vl = *(const uint4*)(tl + off);
            const __half2* ph = (const __half2*)&vh;
            const __half2* pl = (const __half2*)&vl;
#pragma unroll
            for (int j = 0; j < 4; j++) {
                float2 fh = __half22float2(ph[j]);
                float2 fl = __half22float2(pl[j]);
                float w0 = fh.x + fl.x, w1 = fh.y + fl.y;
                int k0 = g * 8 + j * 2;
#pragma unroll
                for (int mm = 0; mm < KBATCH; mm++)
                    acc[mm] += hs[mm][k0] * w0 + hs[mm][k0 + 1] * w1;
            }
        }
#pragma unroll
        for (int mm = 0; mm < KBATCH; mm++)
            atomicAdd(&g_gk[mm][col], acc[mm]);

        grid_bar(&phase);   // all gate adds complete

        if (bid < 32) {
            int i = bid * 256 + tid;
            int mm = i >> 10, nn = i & (HDIM - 1);
            float gi = __ldcg(&g_gk[mm][nn]) + bias[nn];
            float gf = __ldcg(&g_gk[mm][HDIM + nn]) + bias[HDIM + nn];
            float gg = __ldcg(&g_gk[mm][2 * HDIM + nn]) + bias[2 * HDIM + nn];
            float go = __ldcg(&g_gk[mm][3 * HDIM + nn]) + bias[3 * HDIM + nn];
            __stcg(&g_gk[mm][nn], 0.f);
            __stcg(&g_gk[mm][HDIM + nn], 0.f);
            __stcg(&g_gk[mm][2 * HDIM + nn], 0.f);
            __stcg(&g_gk[mm][3 * HDIM + nn], 0.f);
            float cold = g_ck[mm * HDIM + nn];
            float cn = sigmoidf_(gf) * cold + sigmoidf_(gi) * tanhf(gg);
            g_ck[mm * HDIM + nn] = cn;
            __stcg(&g_hk[1 - p][mm * HDIM + nn], sigmoidf_(go) * tanhf(cn));
        }

        grid_bar(&phase);   // h/c published, g_gk cleared
    }
}

__global__ void key_init()
{
    int i = blockIdx.x * blockDim.x + threadIdx.x;
    if (i < KBATCH * HDIM) { g_hk[0][i] = 0.f; g_ck[i] = 0.f; }
    if (i < KBATCH * GDIM) g_gk[i / GDIM][i % GDIM] = 0.f;
    if (i == 0) { g_ticket = 0u; g_kbar = 0u; }
    if (i < TT * MBK) g_dep[i / MBK][i % MBK] = 0u;
}

__global__ void key_mean(int p)
{
    int n = blockIdx.x * blockDim.x + threadIdx.x;
    if (n < HDIM) {
        float sh = 0.f, sc = 0.f;
        for (int m = 0; m < KBATCH; m++) {
            sh += g_hk[p][m * HDIM + n];
            sc += g_ck[m * HDIM + n];
        }
        g_h0[n] = sh * (1.0f / KBATCH);
        g_c0[n] = sc * (1.0f / KBATCH);
    }
}

// broadcast h0/c0 into A tiles + c
__global__ void bcast_init()
{
    int mb = blockIdx.x, ch = blockIdx.y;
    int r = threadIdx.x;
    int m = mb * 128 + r;
    char* th = (char*)&g_Ah[0][mb][ch][0];
#pragma unroll
    for (int kk = 0; kk < KC; kk += 2) {
        int n = ch * KC + kk;
        float v0 = g_h0[n], v1 = g_h0[n + 1];
        *(uint32_t*)(th + aoff(r, kk)) = hpack(v0, v1);
        *(float2*)&g_c[(size_t)m * HDIM + n] = make_float2(g_c0[n], g_c0[n + 1]);
    }
}

// ---------------------------------------------------------------------------
__global__ void classify(const float* __restrict__ Wcls,
                         const float* __restrict__ bcls,
                         float* __restrict__ out)
{
    int gw = (blockIdx.x * blockDim.x + threadIdx.x) >> 5;
    int lane = threadIdx.x & 31;
    if (gw >= BB) return;
    const float* hr = &g_hf[(size_t)gw * HDIM];
    float acc[10];
#pragma unroll
    for (int c = 0; c < 10; c++) acc[c] = 0.f;
    for (int k = lane; k < HDIM; k += 32) {
        float hv = hr[k];
#pragma unroll
        for (int c = 0; c < 10; c++) acc[c] += hv * Wcls[k * 10 + c];
    }
#pragma unroll
    for (int c = 0; c < 10; c++) {
#pragma unroll
        for (int off = 16; off > 0; off >>= 1)
            acc[c] += __shfl_down_sync(0xffffffffu, acc[c], off);
    }
    if (lane == 0) {
#pragma unroll
        for (int c = 0; c < 10; c++)
            out[(size_t)gw * 10 + c] = acc[c] + bcls[c];
    }
}

// ---------------------------------------------------------------------------
extern "C" void kernel_launch(void* const* d_in, const int* in_sizes, int n_in,
                              void* d_out, int out_size)
{
    const float* x    = (const float*)d_in[0];
    const float* key  = (const float*)d_in[1];
    const float* Wih  = (const float*)d_in[2];
    const float* Whh  = (const float*)d_in[3];
    const float* b    = (const float*)d_in[4];
    const float* Wcls = (const float*)d_in[5];
    const float* bcls = (const float*)d_in[6];
    float* out = (float*)d_out;

    cudaFuncSetAttribute(data_persist, cudaFuncAttributeMaxDynamicSharedMemorySize,
                         SMEM_DATA);

    prep_W<<<dim3(CPT, NBK), 256>>>(Wih, Whh);
    prep_x<<<dim3(MBK, TT), 128>>>(x);

    key_init<<<(KBATCH * GDIM + 255) / 256, 256>>>();
    key_persist<<<KGRID, 256>>>(key, b);
    key_mean<<<(HDIM + 255) / 256, 256>>>(0);
    bcast_init<<<dim3(MBK, 16), 128>>>();

    // Data pass: single persistent kernel, device-side scheduling
    data_persist<<<PGRID, 256, SMEM_DATA>>>(b);

    classify<<<BB / 8, 256>>>(Wcls, bcls, out);
}